// round 12
// baseline (speedup 1.0000x reference)
#include <cuda_runtime.h>
#include <cstdint>
#include <cstdio>

// ---------------- problem dims ----------------
#define B8    8
#define N1    1024
#define DD    64
#define HH    4
#define DHH   16
#define DI    128
#define DS    64
#define ROWS  (B8*N1)          // 8192
#define BH    (B8*HH)          // 32
#define T1    1027             // conv1 output length
#define ROWS1 (B8*T1)          // 8216

// ---------------- scratch (static device globals; no allocation) ----------------
__device__ float g_xt   [ROWS*DD];
__device__ float g_wqkv [64*192];
__device__ float g_qkv  [ROWS*192];
__device__ float g_O    [ROWS*DD];
__device__ float g_x1   [ROWS*DD];
__device__ float g_xt2  [ROWS*DD];
__device__ float g_xz   [ROWS*256];
__device__ float g_u    [ROWS*DI];
__device__ float g_xdb  [ROWS*132];
__device__ float g_dt   [ROWS*DI];
__device__ float g_y    [ROWS*DI];
__device__ float g_mg   [ROWS*DD];
__device__ float g_B1   [256*512];      // interleaved (a,gate) columns
__device__ float g_c1bp [512];          // permuted conv1 bias
__device__ float g_h1   [ROWS1*256];
__device__ float g_B2   [1024*64];
__device__ int   g_mask_mode;

// ---------------- helpers ----------------
__device__ __forceinline__ float fast_exp(float x) {
    float t = x * 1.4426950408889634f;
    t = fminf(fmaxf(t, -126.0f), 126.0f);
    float fi = floorf(t);
    float f  = t - fi;
    float p = 0.0018775767f;
    p = fmaf(p, f, 0.0089893397f);
    p = fmaf(p, f, 0.055826318f);
    p = fmaf(p, f, 0.24015361f);
    p = fmaf(p, f, 0.69315308f);
    p = fmaf(p, f, 0.99999994f);
    return p * __int_as_float(((int)fi + 127) << 23);
}
__device__ __forceinline__ float sigmoid_f(float x) { return 1.0f / (1.0f + fast_exp(-x)); }
__device__ __forceinline__ float warp_sum(float v) {
    #pragma unroll
    for (int o = 16; o > 0; o >>= 1) v += __shfl_xor_sync(0xFFFFFFFFu, v, o);
    return v;
}
__device__ __forceinline__ float half_sum(float v) {   // reduce over 16-lane group
    v += __shfl_xor_sync(0xFFFFFFFFu, v, 1);
    v += __shfl_xor_sync(0xFFFFFFFFu, v, 2);
    v += __shfl_xor_sync(0xFFFFFFFFu, v, 4);
    v += __shfl_xor_sync(0xFFFFFFFFu, v, 8);
    return v;
}

// ---------------- init: mask sniff (block 0) + weight builders ----------------
__global__ void init_kernel(const unsigned int* __restrict__ m,
                            const float* __restrict__ Wq, const float* __restrict__ Wkv,
                            const float* __restrict__ c1w, const float* __restrict__ d1w,
                            const float* __restrict__ c1b) {
    if (blockIdx.x == 0) {
        __shared__ int cf, co;
        if (threadIdx.x == 0) { cf = 0; co = 0; }
        __syncthreads();
        int lf = 0, lo = 0;
        for (int k = 0; k < 16; k++) {
            unsigned w = m[threadIdx.x + k * 256];
            if (w == 0x3F800000u) lf++;
            else if (w != 0u && w != 1u) lo++;
        }
        atomicAdd(&cf, lf); atomicAdd(&co, lo);
        __syncthreads();
        if (threadIdx.x == 0)
            g_mask_mode = (cf > 32) ? 0 : ((co > 32) ? 2 : 1);
        return;
    }
    int idx = (blockIdx.x - 1) * 256 + threadIdx.x;
    if (idx < 64 * 192) {
        int k = idx / 192, c = idx % 192;
        g_wqkv[idx] = (c < 64) ? Wq[k * 64 + c] : Wkv[k * 128 + (c - 64)];
        return;
    }
    int i1 = idx - 64 * 192;
    if (i1 < 256 * 512) {
        int r = i1 >> 9, c = i1 & 511;
        int k = c >> 1, half = c & 1;
        int o = k + half * 256;
        int kt = r >> 6, ci = r & 63;
        g_B1[i1] = c1w[o * 256 + ci * 4 + kt];
        return;
    }
    int i2 = i1 - 256 * 512;
    if (i2 < 1024 * 64) {
        int r = i2 >> 6, co2 = i2 & 63;
        int ci = r >> 2, j = r & 3;
        g_B2[i2] = d1w[ci * 256 + co2 * 4 + j];
        return;
    }
    int i3 = i2 - 1024 * 64;
    if (i3 < 512) g_c1bp[i3] = c1b[(i3 >> 1) + (i3 & 1) * 256];
}

// ---------------- layernorm (warp per row of 64) ----------------
__global__ void ln_kernel(const float* __restrict__ x, const float* __restrict__ w,
                          const float* __restrict__ b, float* __restrict__ out, int rows) {
    int warp = (blockIdx.x * blockDim.x + threadIdx.x) >> 5;
    int lane = threadIdx.x & 31;
    if (warp >= rows) return;
    const float* xr = x + (size_t)warp * 64;
    float v0 = xr[lane], v1 = xr[lane + 32];
    float mean = warp_sum(v0 + v1) * (1.0f / 64.0f);
    float d0 = v0 - mean, d1 = v1 - mean;
    float var = warp_sum(d0 * d0 + d1 * d1) * (1.0f / 64.0f);
    float inv = rsqrtf(var + 1e-5f);
    float* orow = out + (size_t)warp * 64;
    orow[lane]      = d0 * inv * w[lane]      + b[lane];
    orow[lane + 32] = d1 * inv * w[lane + 32] + b[lane + 32];
}

// ---------------- templated GEMM: 128x64 tile, 8x4 micro, double-buffered smem
// AMODE 0: A row-major [M,K]
// AMODE 1: conv1 implicit im2col from g_mg (A)
// AMODE 2: conv2 implicit im2col from g_h1 (A)
// AMODE 3: A = (y + u*Dm)*silu(z) on-the-fly (A=g_y, p1=u, p2=xz, p3=Dm)
// EPI 0: C = acc (bounds-checked)
// EPI 1: x1 = 2*p0 + acc + p1[col]; C=x1; q0 = LN(x1; p2,p3)   [requires N=64, M%128==0]
// EPI 2: gated conv1 -> C stride 256, p0 = permuted bias
// EPI 3: leaky + group-RMS(16): p0 = gamma                      [N=64, M%128==0]
// EPI 4: v = p0 + p1 + 0.5*(acc + p2[col]); C = LN(v; p3,p4)    [N=64, M%128==0]
template<int AMODE, int EPI>
__global__ void __launch_bounds__(256, 2)
gemm128t(const float* __restrict__ A, const float* __restrict__ B,
         float* __restrict__ C, int M, int N, int K,
         const float* __restrict__ p0, const float* __restrict__ p1,
         const float* __restrict__ p2, const float* __restrict__ p3,
         const float* __restrict__ p4, float* __restrict__ q0) {
    __shared__ float As[2][16][132];
    __shared__ float Bs[2][16][68];
    int bm0 = blockIdx.y * 128, bn0 = blockIdx.x * 64;
    int tid = threadIdx.x;
    int tx = tid & 15, ty = tid >> 4;

    size_t abase[8];
    int    aaux[8];
    bool   avalid[8];
    #pragma unroll
    for (int i = 0; i < 8; i++) {
        int f = tid + i * 256;
        int gm = bm0 + (f >> 4);
        avalid[i] = (gm < M);
        int gmc = avalid[i] ? gm : 0;
        if (AMODE == 0) {
            abase[i] = (size_t)gmc * K; aaux[i] = 0;
        } else if (AMODE == 1) {
            int b = gmc / 1027;
            int t = gmc - b * 1027;
            abase[i] = (size_t)(b << 10) * 64; aaux[i] = t;
        } else if (AMODE == 2) {
            int b = gmc >> 10, s = gmc & 1023;
            abase[i] = ((size_t)b * 1027 + s) * 256; aaux[i] = 0;
        } else {
            abase[i] = (size_t)gmc * 128; aaux[i] = gmc * 256 + 128;
        }
    }

    float ra[8], rb[4];
    auto fetch = [&](int k0) {
        #pragma unroll
        for (int i = 0; i < 8; i++) {
            int f = tid + i * 256;
            int kk = f & 15;
            int k = k0 + kk;
            float v = 0.0f;
            if (AMODE == 0) {
                if (avalid[i]) v = A[abase[i] + k];
            } else if (AMODE == 1) {
                int kt = k >> 6, ci = k & 63;
                int s = aaux[i] + kt - 3;
                if (avalid[i] && s >= 0 && s < 1024) v = A[abase[i] + (size_t)s * 64 + ci];
            } else if (AMODE == 2) {
                int ci = k >> 2, j = k & 3;
                if (avalid[i]) v = A[abase[i] + (size_t)(3 - j) * 256 + ci];
            } else {
                if (avalid[i]) {
                    float y  = A[abase[i] + k];
                    float uu = p1[abase[i] + k];
                    float z  = p2[aaux[i] + k];
                    v = (y + uu * p3[k]) * (z * sigmoid_f(z));
                }
            }
            ra[i] = v;
        }
        #pragma unroll
        for (int i = 0; i < 4; i++) {
            int f = tid + i * 256;
            int kk = f >> 6, n = f & 63;
            int gn = bn0 + n;
            rb[i] = (gn < N) ? B[(size_t)(k0 + kk) * N + gn] : 0.0f;
        }
    };
    auto stage = [&](int buf) {
        #pragma unroll
        for (int i = 0; i < 8; i++) {
            int f = tid + i * 256;
            As[buf][f & 15][f >> 4] = ra[i];
        }
        #pragma unroll
        for (int i = 0; i < 4; i++) {
            int f = tid + i * 256;
            Bs[buf][f >> 6][f & 63] = rb[i];
        }
    };

    fetch(0);
    stage(0);
    __syncthreads();

    float acc[8][4] = {};
    int T = K >> 4;
    for (int t = 0; t < T; t++) {
        int buf = t & 1;
        if (t + 1 < T) fetch((t + 1) << 4);
        #pragma unroll
        for (int kk = 0; kk < 16; kk++) {
            float4 a0 = *(const float4*)&As[buf][kk][ty * 8];
            float4 a1 = *(const float4*)&As[buf][kk][ty * 8 + 4];
            float4 b4 = *(const float4*)&Bs[buf][kk][tx * 4];
            float av[8] = {a0.x, a0.y, a0.z, a0.w, a1.x, a1.y, a1.z, a1.w};
            float bv[4] = {b4.x, b4.y, b4.z, b4.w};
            #pragma unroll
            for (int r = 0; r < 8; r++)
                #pragma unroll
                for (int c = 0; c < 4; c++)
                    acc[r][c] = fmaf(av[r], bv[c], acc[r][c]);
        }
        if (t + 1 < T) stage(buf ^ 1);
        __syncthreads();
    }

    if (EPI == 0) {
        #pragma unroll
        for (int r = 0; r < 8; r++) {
            int gm = bm0 + ty * 8 + r;
            if (gm < M) {
                #pragma unroll
                for (int c = 0; c < 4; c++) {
                    int gn = bn0 + tx * 4 + c;
                    if (gn < N) C[(size_t)gm * N + gn] = acc[r][c];
                }
            }
        }
    } else if (EPI == 1) {
        // x1 = 2*x + acc + bo; write x1; q0 = LN2(x1)
        #pragma unroll
        for (int r = 0; r < 8; r++) {
            int gm = bm0 + ty * 8 + r;
            float v[4];
            #pragma unroll
            for (int c = 0; c < 4; c++) {
                int gn = tx * 4 + c;
                v[c] = 2.0f * p0[(size_t)gm * 64 + gn] + acc[r][c] + p1[gn];
                C[(size_t)gm * 64 + gn] = v[c];
            }
            float s = half_sum(v[0] + v[1] + v[2] + v[3]);
            float mean = s * (1.0f / 64.0f);
            float d[4], ss = 0.0f;
            #pragma unroll
            for (int c = 0; c < 4; c++) { d[c] = v[c] - mean; ss = fmaf(d[c], d[c], ss); }
            ss = half_sum(ss);
            float inv = rsqrtf(ss * (1.0f / 64.0f) + 1e-5f);
            #pragma unroll
            for (int c = 0; c < 4; c++) {
                int gn = tx * 4 + c;
                q0[(size_t)gm * 64 + gn] = d[c] * inv * p2[gn] + p3[gn];
            }
        }
    } else if (EPI == 2) {
        int gn = bn0 + tx * 4;
        float ba0 = p0[gn + 0], bg0 = p0[gn + 1], ba1 = p0[gn + 2], bg1 = p0[gn + 3];
        int hc = gn >> 1;
        #pragma unroll
        for (int r = 0; r < 8; r++) {
            int gm = bm0 + ty * 8 + r;
            if (gm < M) {
                float a0 = acc[r][0] + ba0;
                float gg0 = acc[r][1] + bg0;
                float a1 = acc[r][2] + ba1;
                float gg1 = acc[r][3] + bg1;
                float h0 = a0 * (gg0 * sigmoid_f(gg0));
                float h1v = a1 * (gg1 * sigmoid_f(gg1));
                *(float2*)&C[(size_t)gm * 256 + hc] = make_float2(h0, h1v);
            }
        }
    } else if (EPI == 3) {
        #pragma unroll
        for (int r = 0; r < 8; r++) {
            int gm = bm0 + ty * 8 + r;
            float v[4], ss = 0.0f;
            #pragma unroll
            for (int c = 0; c < 4; c++) {
                float xv = acc[r][c];
                xv = (xv >= 0.0f) ? xv : 0.01f * xv;
                v[c] = xv; ss = fmaf(xv, xv, ss);
            }
            ss += __shfl_xor_sync(0xFFFFFFFFu, ss, 1);
            ss += __shfl_xor_sync(0xFFFFFFFFu, ss, 2);
            float sc = 1.0f / (sqrtf(ss) * 0.25f + 1e-5f);
            #pragma unroll
            for (int c = 0; c < 4; c++) {
                int gn = tx * 4 + c;
                C[(size_t)gm * 64 + gn] = v[c] * sc * p0[gn];
            }
        }
    } else {
        // EPI 4: v = x1 + mg + 0.5*(acc + d1b); C = LN3(v)
        #pragma unroll
        for (int r = 0; r < 8; r++) {
            int gm = bm0 + ty * 8 + r;
            float v[4];
            #pragma unroll
            for (int c = 0; c < 4; c++) {
                int gn = tx * 4 + c;
                size_t ix = (size_t)gm * 64 + gn;
                v[c] = p0[ix] + p1[ix] + 0.5f * (acc[r][c] + p2[gn]);
            }
            float s = half_sum(v[0] + v[1] + v[2] + v[3]);
            float mean = s * (1.0f / 64.0f);
            float d[4], ss = 0.0f;
            #pragma unroll
            for (int c = 0; c < 4; c++) { d[c] = v[c] - mean; ss = fmaf(d[c], d[c], ss); }
            ss = half_sum(ss);
            float inv = rsqrtf(ss * (1.0f / 64.0f) + 1e-5f);
            #pragma unroll
            for (int c = 0; c < 4; c++) {
                int gn = tx * 4 + c;
                C[(size_t)gm * 64 + gn] = d[c] * inv * p3[gn] + p4[gn];
            }
        }
    }
}

// ---------------- fused flash attention (vectorized e_sh PV; lean accumulators) --
// Block: 64-row i-tile for one (b,h). 256 thr = 16 ty (4 rows) x 16 tx.
// Scores: tx = 4-col j-group; rel loaded as 2 aligned float4 (lbase % 4 == 0).
// PV: remap tx -> (txd = tx>>2 : 4 d's) x (txj = tx&3 : j in [txj*16, txj*16+16)),
//     all e/v accesses are aligned float4; acc[4][4]; 2-shuffle end reduction.
__global__ void __launch_bounds__(256, 3)
flash_kernel(const float* __restrict__ qkv, const float* __restrict__ relemb,
             const void* __restrict__ mask, float* __restrict__ O) {
    int it = blockIdx.x, bh = blockIdx.y;
    int b = bh >> 2, h = bh & 3;
    int i0 = it * 64;
    __shared__ float qT[16][68];
    __shared__ float kT[16][68];
    __shared__ float vT[16][68];
    __shared__ float relT[16][132];
    __shared__ float e_sh[64][68];
    int tid = threadIdx.x, tx = tid & 15, ty = tid >> 4;
    int txj = tx & 3, txd = tx >> 2;
    int mode = g_mask_mode;

    const float* qb = qkv + (size_t)(b * 1024 + i0) * 192 + h * 16;
    for (int f = tid; f < 1024; f += 256) { int r = f >> 4, d = f & 15; qT[d][r] = qb[r * 192 + d]; }

    float acc[4][4] = {};
    float rsum[4] = {};
    int lbase = (ty - tx) * 4 + 60;   // multiple of 4 -> aligned float4 loads

    for (int jt = 0; jt < 16; jt++) {
        int j0 = jt * 64;
        __syncthreads();   // prev PV done with e_sh/vT; qT ready on first iter
        const float* kb = qkv + (size_t)(b * 1024 + j0) * 192 + 64 + h * 16;
        for (int f = tid; f < 1024; f += 256) {
            int r = f >> 4, d = f & 15;
            kT[d][r] = kb[r * 192 + d];
            vT[d][r] = kb[r * 192 + 64 + d];
        }
        int pbase = i0 - j0 + 449;
        for (int f = tid; f < 127 * 16; f += 256) {
            int m = f >> 4, d = f & 15;
            int p = min(max(pbase + m, 0), 1024);
            relT[d][m] = relemb[p * 16 + d];
        }
        __syncthreads();

        // ---- scores (tx = j-group mapping) ----
        float s[4][4] = {};
        #pragma unroll
        for (int d = 0; d < 16; d++) {
            float4 aq4 = *(const float4*)&qT[d][ty * 4];
            float4 bk4 = *(const float4*)&kT[d][tx * 4];
            float4 rl0 = *(const float4*)&relT[d][lbase];
            float4 rl1 = *(const float4*)&relT[d][lbase + 4];
            float aq[4] = {aq4.x, aq4.y, aq4.z, aq4.w};
            float bk[4] = {bk4.x, bk4.y, bk4.z, bk4.w};
            float rl[7] = {rl0.x, rl0.y, rl0.z, rl0.w, rl1.x, rl1.y, rl1.z};
            #pragma unroll
            for (int r = 0; r < 4; r++)
                #pragma unroll
                for (int c = 0; c < 4; c++)
                    s[r][c] = fmaf(aq[r], bk[c] + rl[r - c + 3], s[r][c]);
        }

        size_t mbase = ((size_t)bh * 1024 + i0 + ty * 4) * 1024 + j0 + tx * 4;
        #pragma unroll
        for (int r = 0; r < 4; r++) {
            size_t mo = mbase + (size_t)r * 1024;
            bool m0, m1, m2, m3;
            if (mode == 0) {
                float4 mv = *(const float4*)((const float*)mask + mo);
                m0 = mv.x != 0.0f; m1 = mv.y != 0.0f; m2 = mv.z != 0.0f; m3 = mv.w != 0.0f;
            } else if (mode == 1) {
                int4 mv = *(const int4*)((const int*)mask + mo);
                m0 = mv.x != 0; m1 = mv.y != 0; m2 = mv.z != 0; m3 = mv.w != 0;
            } else {
                unsigned mv = *(const unsigned*)((const unsigned char*)mask + mo);
                m0 = (mv & 0xFFu) != 0; m1 = (mv & 0xFF00u) != 0;
                m2 = (mv & 0xFF0000u) != 0; m3 = (mv & 0xFF000000u) != 0;
            }
            float4 e4;
            e4.x = m0 ? 0.0f : fast_exp(s[r][0] * 0.25f);
            e4.y = m1 ? 0.0f : fast_exp(s[r][1] * 0.25f);
            e4.z = m2 ? 0.0f : fast_exp(s[r][2] * 0.25f);
            e4.w = m3 ? 0.0f : fast_exp(s[r][3] * 0.25f);
            rsum[r] += e4.x + e4.y + e4.z + e4.w;
            *(float4*)&e_sh[ty * 4 + r][tx * 4] = e4;
        }
        __syncthreads();

        // ---- PV (vectorized float4; thread covers j in [txj*16, txj*16+16)) ----
        int jb = txj * 16;
        #pragma unroll
        for (int jc4 = 0; jc4 < 4; jc4++) {
            int jj = jb + jc4 * 4;
            float4 e0 = *(const float4*)&e_sh[ty * 4 + 0][jj];
            float4 e1 = *(const float4*)&e_sh[ty * 4 + 1][jj];
            float4 e2 = *(const float4*)&e_sh[ty * 4 + 2][jj];
            float4 e3 = *(const float4*)&e_sh[ty * 4 + 3][jj];
            #pragma unroll
            for (int dd = 0; dd < 4; dd++) {
                float4 v4 = *(const float4*)&vT[txd * 4 + dd][jj];
                acc[0][dd] = fmaf(e0.x, v4.x, fmaf(e0.y, v4.y, fmaf(e0.z, v4.z, fmaf(e0.w, v4.w, acc[0][dd]))));
                acc[1][dd] = fmaf(e1.x, v4.x, fmaf(e1.y, v4.y, fmaf(e1.z, v4.z, fmaf(e1.w, v4.w, acc[1][dd]))));
                acc[2][dd] = fmaf(e2.x, v4.x, fmaf(e2.y, v4.y, fmaf(e2.z, v4.z, fmaf(e2.w, v4.w, acc[2][dd]))));
                acc[3][dd] = fmaf(e3.x, v4.x, fmaf(e3.y, v4.y, fmaf(e3.z, v4.z, fmaf(e3.w, v4.w, acc[3][dd]))));
            }
        }
    }

    // rowsum: reduce over all 16 tx lanes (disjoint j coverage in score phase)
    #pragma unroll
    for (int r = 0; r < 4; r++) rsum[r] = half_sum(rsum[r]);
    // acc: reduce over the 4 txj lanes sharing (ty, txd)
    #pragma unroll
    for (int r = 0; r < 4; r++)
        #pragma unroll
        for (int dd = 0; dd < 4; dd++) {
            float v = acc[r][dd];
            v += __shfl_xor_sync(0xFFFFFFFFu, v, 1);
            v += __shfl_xor_sync(0xFFFFFFFFu, v, 2);
            acc[r][dd] = v;
        }
    if (txj == 0) {
        #pragma unroll
        for (int r = 0; r < 4; r++) {
            float inv = 1.0f / rsum[r];
            float4 o4 = make_float4(acc[r][0] * inv, acc[r][1] * inv,
                                    acc[r][2] * inv, acc[r][3] * inv);
            *(float4*)&O[(size_t)(b * 1024 + i0 + ty * 4 + r) * 64 + h * 16 + txd * 4] = o4;
        }
    }
}

// ---------------- remaining elementwise stages ----------------
__global__ void convsilu_kernel(const float* __restrict__ convw, const float* __restrict__ convb) {
    int idx = blockIdx.x * blockDim.x + threadIdx.x;
    if (idx >= ROWS * DI) return;
    int d = idx & 127, t = (idx >> 7) & 1023, b = idx >> 17;
    float acc = convb[d];
    #pragma unroll
    for (int k = 0; k < 4; k++) {
        int s = t + k - 3;
        if (s >= 0) acc = fmaf(g_xz[(size_t)((b << 10) + s) * 256 + d], convw[d * 4 + k], acc);
    }
    g_u[idx] = acc * sigmoid_f(acc);
}
__global__ void dtprep_kernel(const float* __restrict__ Wdt, const float* __restrict__ bdt) {
    int idx = blockIdx.x * blockDim.x + threadIdx.x;
    if (idx >= ROWS * DI) return;
    int d = idx & 127, bt = idx >> 7;
    float x = bdt[d];
    #pragma unroll
    for (int r = 0; r < 4; r++) x = fmaf(g_xdb[(size_t)bt * 132 + r], Wdt[r * 128 + d], x);
    g_dt[idx] = (x > 20.0f) ? x : log1pf(fast_exp(x));
}
__global__ void scan_kernel(const float* __restrict__ Alog) {
    int w = (blockIdx.x * blockDim.x + threadIdx.x) >> 5;
    int lane = threadIdx.x & 31;
    int b = w >> 7, d = w & 127;
    float A0 = -__expf(Alog[d * 64 + lane]);
    float A1 = -__expf(Alog[d * 64 + lane + 32]);
    float h0 = 0.0f, h1 = 0.0f;
    const float* dtp = g_dt + (size_t)b * 1024 * 128 + d;
    const float* up  = g_u  + (size_t)b * 1024 * 128 + d;
    const float* xp  = g_xdb + (size_t)b * 1024 * 132;
    float* yp = g_y + (size_t)b * 1024 * 128 + d;
    #pragma unroll 4
    for (int t = 0; t < 1024; t++) {
        float dtv = dtp[t << 7];
        float uv  = up[t << 7];
        float B0 = xp[t * 132 + 4 + lane],  B1 = xp[t * 132 + 36 + lane];
        float C0 = xp[t * 132 + 68 + lane], C1 = xp[t * 132 + 100 + lane];
        float du = dtv * uv;
        h0 = fmaf(h0, __expf(dtv * A0), du * B0);
        h1 = fmaf(h1, __expf(dtv * A1), du * B1);
        float p = fmaf(h0, C0, h1 * C1);
        p = warp_sum(p);
        if (lane == 0) yp[t << 7] = p;
    }
}

// ---------------- launch ----------------
static void* dev_ptr(const void* sym) { void* p = nullptr; cudaGetSymbolAddress(&p, sym); return p; }

extern "C" void kernel_launch(void* const* d_in, const int* in_sizes, int n_in,
                              void* d_out, int out_size) {
    const float* x      = (const float*)d_in[0];
    const void*  dmask  = d_in[1];
    const float* ln1w   = (const float*)d_in[2];
    const float* ln1b   = (const float*)d_in[3];
    const float* Wq     = (const float*)d_in[4];
    const float* Wkv    = (const float*)d_in[5];
    const float* Wo     = (const float*)d_in[6];
    const float* bo     = (const float*)d_in[7];
    const float* relemb = (const float*)d_in[8];
    const float* ln2w   = (const float*)d_in[9];
    const float* ln2b   = (const float*)d_in[10];
    const float* Win    = (const float*)d_in[11];
    const float* convw  = (const float*)d_in[12];
    const float* convb  = (const float*)d_in[13];
    const float* Wxproj = (const float*)d_in[14];
    const float* Wdt    = (const float*)d_in[15];
    const float* bdt    = (const float*)d_in[16];
    const float* Alog   = (const float*)d_in[17];
    const float* Dm     = (const float*)d_in[18];
    const float* Wout   = (const float*)d_in[19];
    const float* gamma  = (const float*)d_in[20];
    const float* c1w    = (const float*)d_in[21];
    const float* c1b    = (const float*)d_in[22];
    const float* d1w    = (const float*)d_in[23];
    const float* d1b    = (const float*)d_in[24];
    const float* ln3w   = (const float*)d_in[25];
    const float* ln3b   = (const float*)d_in[26];
    float* out = (float*)d_out;

    float* p_xt    = (float*)dev_ptr(g_xt);
    float* p_wqkv  = (float*)dev_ptr(g_wqkv);
    float* p_qkv   = (float*)dev_ptr(g_qkv);
    float* p_O     = (float*)dev_ptr(g_O);
    float* p_x1    = (float*)dev_ptr(g_x1);
    float* p_xt2   = (float*)dev_ptr(g_xt2);
    float* p_xz    = (float*)dev_ptr(g_xz);
    float* p_u     = (float*)dev_ptr(g_u);
    float* p_xdb   = (float*)dev_ptr(g_xdb);
    float* p_y     = (float*)dev_ptr(g_y);
    float* p_mg    = (float*)dev_ptr(g_mg);
    float* p_B1    = (float*)dev_ptr(g_B1);
    float* p_c1bp  = (float*)dev_ptr(g_c1bp);
    float* p_h1    = (float*)dev_ptr(g_h1);
    float* p_B2    = (float*)dev_ptr(g_B2);

    // 0: mask sniff + all weight rearrangement (one launch)
    int build_elems = 64*192 + 256*512 + 1024*64 + 512;
    init_kernel<<<1 + (build_elems + 255) / 256, 256>>>(
        (const unsigned int*)dmask, Wq, Wkv, c1w, d1w, c1b);

    // 1: LN1 + QKV projection
    ln_kernel<<<1024, 256>>>(x, ln1w, ln1b, p_xt, ROWS);
    gemm128t<0,0><<<dim3(3, 64), 256>>>(p_xt, p_wqkv, p_qkv, ROWS, 192, 64,
                                        nullptr, nullptr, nullptr, nullptr, nullptr, nullptr);

    // 2: fused flash attention
    flash_kernel<<<dim3(16, BH), 256>>>(p_qkv, relemb, dmask, p_O);

    // 3: Wo proj + bias + double residual + LN2 (one kernel) -> g_x1, g_xt2
    gemm128t<0,1><<<dim3(1, 64), 256>>>(p_O, Wo, p_x1, ROWS, 64, 64,
                                        x, bo, ln2w, ln2b, nullptr, p_xt2);

    // 4: Mamba
    gemm128t<0,0><<<dim3(4, 64), 256>>>(p_xt2, Win, p_xz, ROWS, 256, 64,
                                        nullptr, nullptr, nullptr, nullptr, nullptr, nullptr);
    convsilu_kernel<<<(ROWS * DI + 255) / 256, 256>>>(convw, convb);
    gemm128t<0,0><<<dim3(3, 64), 256>>>(p_u, Wxproj, p_xdb, ROWS, 132, DI,
                                        nullptr, nullptr, nullptr, nullptr, nullptr, nullptr);
    dtprep_kernel<<<(ROWS * DI + 255) / 256, 256>>>(Wdt, bdt);
    scan_kernel<<<128, 256>>>(Alog);
    // Wout: on-the-fly ym (amode3) + leaky+groupRMS (epi3) -> g_mg
    gemm128t<3,3><<<dim3(1, 64), 256>>>(p_y, Wout, p_mg, ROWS, 64, DI,
                                        gamma, p_u, p_xz, Dm, nullptr, nullptr);

    // 5: FF — conv1 (implicit im2col + gated epilogue) -> h1
    gemm128t<1,2><<<dim3(8, 65), 256>>>(p_mg, p_B1, p_h1, ROWS1, 512, 256,
                                        p_c1bp, nullptr, nullptr, nullptr, nullptr, nullptr);
    //    conv2 + final residual + LN3 -> out
    gemm128t<2,4><<<dim3(1, 64), 256>>>(p_h1, p_B2, out, ROWS, 64, 1024,
                                        p_x1, p_mg, d1b, ln3w, ln3b, nullptr);

    (void)in_sizes; (void)n_in; (void)out_size;
}

// round 13
// speedup vs baseline: 1.2216x; 1.2216x over previous
#include <cuda_runtime.h>
#include <cstdint>
#include <cstdio>

// ---------------- problem dims ----------------
#define B8    8
#define N1    1024
#define DD    64
#define HH    4
#define DHH   16
#define DI    128
#define DS    64
#define ROWS  (B8*N1)          // 8192
#define BH    (B8*HH)          // 32
#define T1    1027             // conv1 output length
#define ROWS1 (B8*T1)          // 8216

// ---------------- scratch (static device globals; no allocation) ----------------
__device__ float g_xt   [ROWS*DD];
__device__ float g_wqkv [64*192];
__device__ float g_qkv  [ROWS*192];
__device__ float g_O    [ROWS*DD];
__device__ float g_x1   [ROWS*DD];
__device__ float g_xt2  [ROWS*DD];
__device__ float g_xz   [ROWS*256];
__device__ float g_u    [ROWS*DI];
__device__ float g_xdb  [ROWS*132];
__device__ float g_dt   [ROWS*DI];
__device__ float g_y    [ROWS*DI];
__device__ float g_mg   [ROWS*DD];
__device__ float g_B1   [256*512];      // interleaved (a,gate) columns
__device__ float g_c1bp [512];          // permuted conv1 bias
__device__ float g_h1   [ROWS1*256];
__device__ float g_B2   [1024*64];
__device__ unsigned g_maskbits[BH*N1*32];   // 1 bit per (bh,i,j); 32 words per row
__device__ int   g_mask_mode;

// ---------------- helpers ----------------
__device__ __forceinline__ float fast_exp(float x) {
    float t = x * 1.4426950408889634f;
    t = fminf(fmaxf(t, -126.0f), 126.0f);
    float fi = floorf(t);
    float f  = t - fi;
    float p = 0.0018775767f;
    p = fmaf(p, f, 0.0089893397f);
    p = fmaf(p, f, 0.055826318f);
    p = fmaf(p, f, 0.24015361f);
    p = fmaf(p, f, 0.69315308f);
    p = fmaf(p, f, 0.99999994f);
    return p * __int_as_float(((int)fi + 127) << 23);
}
__device__ __forceinline__ float sigmoid_f(float x) { return 1.0f / (1.0f + fast_exp(-x)); }
__device__ __forceinline__ float warp_sum(float v) {
    #pragma unroll
    for (int o = 16; o > 0; o >>= 1) v += __shfl_xor_sync(0xFFFFFFFFu, v, o);
    return v;
}
__device__ __forceinline__ float half_sum(float v) {   // reduce over 16-lane group
    v += __shfl_xor_sync(0xFFFFFFFFu, v, 1);
    v += __shfl_xor_sync(0xFFFFFFFFu, v, 2);
    v += __shfl_xor_sync(0xFFFFFFFFu, v, 4);
    v += __shfl_xor_sync(0xFFFFFFFFu, v, 8);
    return v;
}

// ---------------- init: mask sniff (block 0) + weight builders ----------------
__global__ void init_kernel(const unsigned int* __restrict__ m,
                            const float* __restrict__ Wq, const float* __restrict__ Wkv,
                            const float* __restrict__ c1w, const float* __restrict__ d1w,
                            const float* __restrict__ c1b) {
    if (blockIdx.x == 0) {
        __shared__ int cf, co;
        if (threadIdx.x == 0) { cf = 0; co = 0; }
        __syncthreads();
        int lf = 0, lo = 0;
        for (int k = 0; k < 16; k++) {
            unsigned w = m[threadIdx.x + k * 256];
            if (w == 0x3F800000u) lf++;
            else if (w != 0u && w != 1u) lo++;
        }
        atomicAdd(&cf, lf); atomicAdd(&co, lo);
        __syncthreads();
        if (threadIdx.x == 0)
            g_mask_mode = (cf > 32) ? 0 : ((co > 32) ? 2 : 1);
        return;
    }
    int idx = (blockIdx.x - 1) * 256 + threadIdx.x;
    if (idx < 64 * 192) {
        int k = idx / 192, c = idx % 192;
        g_wqkv[idx] = (c < 64) ? Wq[k * 64 + c] : Wkv[k * 128 + (c - 64)];
        return;
    }
    int i1 = idx - 64 * 192;
    if (i1 < 256 * 512) {
        int r = i1 >> 9, c = i1 & 511;
        int k = c >> 1, half = c & 1;
        int o = k + half * 256;
        int kt = r >> 6, ci = r & 63;
        g_B1[i1] = c1w[o * 256 + ci * 4 + kt];
        return;
    }
    int i2 = i1 - 256 * 512;
    if (i2 < 1024 * 64) {
        int r = i2 >> 6, co2 = i2 & 63;
        int ci = r >> 2, j = r & 3;
        g_B2[i2] = d1w[ci * 256 + co2 * 4 + j];
        return;
    }
    int i3 = i2 - 1024 * 64;
    if (i3 < 512) g_c1bp[i3] = c1b[(i3 >> 1) + (i3 & 1) * 256];
}

// ---------------- mask -> bitmask (perfectly coalesced ballot stream) ----------
// warp w handles words w*32 .. w*32+31 (elements w*1024 .. w*1024+1023)
__global__ void maskbits_kernel(const void* __restrict__ mask) {
    int warp = (blockIdx.x * blockDim.x + threadIdx.x) >> 5;
    int lane = threadIdx.x & 31;
    int mode = g_mask_mode;
    size_t ebase = (size_t)warp * 1024;
    #pragma unroll 4
    for (int k = 0; k < 32; k++) {
        size_t e = ebase + (size_t)k * 32 + lane;
        bool bit;
        if (mode == 0)      bit = ((const float*)mask)[e] != 0.0f;
        else if (mode == 1) bit = ((const int*)mask)[e] != 0;
        else                bit = ((const unsigned char*)mask)[e] != 0;
        unsigned w = __ballot_sync(0xFFFFFFFFu, bit);
        if (lane == 0) g_maskbits[warp * 32 + k] = w;
    }
}

// ---------------- layernorm (warp per row of 64) ----------------
__global__ void ln_kernel(const float* __restrict__ x, const float* __restrict__ w,
                          const float* __restrict__ b, float* __restrict__ out, int rows) {
    int warp = (blockIdx.x * blockDim.x + threadIdx.x) >> 5;
    int lane = threadIdx.x & 31;
    if (warp >= rows) return;
    const float* xr = x + (size_t)warp * 64;
    float v0 = xr[lane], v1 = xr[lane + 32];
    float mean = warp_sum(v0 + v1) * (1.0f / 64.0f);
    float d0 = v0 - mean, d1 = v1 - mean;
    float var = warp_sum(d0 * d0 + d1 * d1) * (1.0f / 64.0f);
    float inv = rsqrtf(var + 1e-5f);
    float* orow = out + (size_t)warp * 64;
    orow[lane]      = d0 * inv * w[lane]      + b[lane];
    orow[lane + 32] = d1 * inv * w[lane + 32] + b[lane + 32];
}

// ---------------- templated GEMM: 128x64 tile, 8x4 micro, double-buffered smem
// AMODE 0: A row-major [M,K]
// AMODE 1: conv1 implicit im2col from g_mg (A)
// AMODE 2: conv2 implicit im2col from g_h1 (A)
// AMODE 3: A = (y + u*Dm)*silu(z) on-the-fly (A=g_y, p1=u, p2=xz, p3=Dm)
// EPI 0: C = acc (bounds-checked)
// EPI 1: x1 = 2*p0 + acc + p1[col]; C=x1; q0 = LN(x1; p2,p3)   [requires N=64, M%128==0]
// EPI 2: gated conv1 -> C stride 256, p0 = permuted bias
// EPI 3: leaky + group-RMS(16): p0 = gamma                      [N=64, M%128==0]
// EPI 4: v = p0 + p1 + 0.5*(acc + p2[col]); C = LN(v; p3,p4)    [N=64, M%128==0]
template<int AMODE, int EPI>
__global__ void __launch_bounds__(256, 2)
gemm128t(const float* __restrict__ A, const float* __restrict__ B,
         float* __restrict__ C, int M, int N, int K,
         const float* __restrict__ p0, const float* __restrict__ p1,
         const float* __restrict__ p2, const float* __restrict__ p3,
         const float* __restrict__ p4, float* __restrict__ q0) {
    __shared__ float As[2][16][132];
    __shared__ float Bs[2][16][68];
    int bm0 = blockIdx.y * 128, bn0 = blockIdx.x * 64;
    int tid = threadIdx.x;
    int tx = tid & 15, ty = tid >> 4;

    size_t abase[8];
    int    aaux[8];
    bool   avalid[8];
    #pragma unroll
    for (int i = 0; i < 8; i++) {
        int f = tid + i * 256;
        int gm = bm0 + (f >> 4);
        avalid[i] = (gm < M);
        int gmc = avalid[i] ? gm : 0;
        if (AMODE == 0) {
            abase[i] = (size_t)gmc * K; aaux[i] = 0;
        } else if (AMODE == 1) {
            int b = gmc / 1027;
            int t = gmc - b * 1027;
            abase[i] = (size_t)(b << 10) * 64; aaux[i] = t;
        } else if (AMODE == 2) {
            int b = gmc >> 10, s = gmc & 1023;
            abase[i] = ((size_t)b * 1027 + s) * 256; aaux[i] = 0;
        } else {
            abase[i] = (size_t)gmc * 128; aaux[i] = gmc * 256 + 128;
        }
    }

    float ra[8], rb[4];
    auto fetch = [&](int k0) {
        #pragma unroll
        for (int i = 0; i < 8; i++) {
            int f = tid + i * 256;
            int kk = f & 15;
            int k = k0 + kk;
            float v = 0.0f;
            if (AMODE == 0) {
                if (avalid[i]) v = A[abase[i] + k];
            } else if (AMODE == 1) {
                int kt = k >> 6, ci = k & 63;
                int s = aaux[i] + kt - 3;
                if (avalid[i] && s >= 0 && s < 1024) v = A[abase[i] + (size_t)s * 64 + ci];
            } else if (AMODE == 2) {
                int ci = k >> 2, j = k & 3;
                if (avalid[i]) v = A[abase[i] + (size_t)(3 - j) * 256 + ci];
            } else {
                if (avalid[i]) {
                    float y  = A[abase[i] + k];
                    float uu = p1[abase[i] + k];
                    float z  = p2[aaux[i] + k];
                    v = (y + uu * p3[k]) * (z * sigmoid_f(z));
                }
            }
            ra[i] = v;
        }
        #pragma unroll
        for (int i = 0; i < 4; i++) {
            int f = tid + i * 256;
            int kk = f >> 6, n = f & 63;
            int gn = bn0 + n;
            rb[i] = (gn < N) ? B[(size_t)(k0 + kk) * N + gn] : 0.0f;
        }
    };
    auto stage = [&](int buf) {
        #pragma unroll
        for (int i = 0; i < 8; i++) {
            int f = tid + i * 256;
            As[buf][f & 15][f >> 4] = ra[i];
        }
        #pragma unroll
        for (int i = 0; i < 4; i++) {
            int f = tid + i * 256;
            Bs[buf][f >> 6][f & 63] = rb[i];
        }
    };

    fetch(0);
    stage(0);
    __syncthreads();

    float acc[8][4] = {};
    int T = K >> 4;
    for (int t = 0; t < T; t++) {
        int buf = t & 1;
        if (t + 1 < T) fetch((t + 1) << 4);
        #pragma unroll
        for (int kk = 0; kk < 16; kk++) {
            float4 a0 = *(const float4*)&As[buf][kk][ty * 8];
            float4 a1 = *(const float4*)&As[buf][kk][ty * 8 + 4];
            float4 b4 = *(const float4*)&Bs[buf][kk][tx * 4];
            float av[8] = {a0.x, a0.y, a0.z, a0.w, a1.x, a1.y, a1.z, a1.w};
            float bv[4] = {b4.x, b4.y, b4.z, b4.w};
            #pragma unroll
            for (int r = 0; r < 8; r++)
                #pragma unroll
                for (int c = 0; c < 4; c++)
                    acc[r][c] = fmaf(av[r], bv[c], acc[r][c]);
        }
        if (t + 1 < T) stage(buf ^ 1);
        __syncthreads();
    }

    if (EPI == 0) {
        #pragma unroll
        for (int r = 0; r < 8; r++) {
            int gm = bm0 + ty * 8 + r;
            if (gm < M) {
                #pragma unroll
                for (int c = 0; c < 4; c++) {
                    int gn = bn0 + tx * 4 + c;
                    if (gn < N) C[(size_t)gm * N + gn] = acc[r][c];
                }
            }
        }
    } else if (EPI == 1) {
        // x1 = 2*x + acc + bo; write x1; q0 = LN2(x1)
        #pragma unroll
        for (int r = 0; r < 8; r++) {
            int gm = bm0 + ty * 8 + r;
            float v[4];
            #pragma unroll
            for (int c = 0; c < 4; c++) {
                int gn = tx * 4 + c;
                v[c] = 2.0f * p0[(size_t)gm * 64 + gn] + acc[r][c] + p1[gn];
                C[(size_t)gm * 64 + gn] = v[c];
            }
            float s = half_sum(v[0] + v[1] + v[2] + v[3]);
            float mean = s * (1.0f / 64.0f);
            float d[4], ss = 0.0f;
            #pragma unroll
            for (int c = 0; c < 4; c++) { d[c] = v[c] - mean; ss = fmaf(d[c], d[c], ss); }
            ss = half_sum(ss);
            float inv = rsqrtf(ss * (1.0f / 64.0f) + 1e-5f);
            #pragma unroll
            for (int c = 0; c < 4; c++) {
                int gn = tx * 4 + c;
                q0[(size_t)gm * 64 + gn] = d[c] * inv * p2[gn] + p3[gn];
            }
        }
    } else if (EPI == 2) {
        int gn = bn0 + tx * 4;
        float ba0 = p0[gn + 0], bg0 = p0[gn + 1], ba1 = p0[gn + 2], bg1 = p0[gn + 3];
        int hc = gn >> 1;
        #pragma unroll
        for (int r = 0; r < 8; r++) {
            int gm = bm0 + ty * 8 + r;
            if (gm < M) {
                float a0 = acc[r][0] + ba0;
                float gg0 = acc[r][1] + bg0;
                float a1 = acc[r][2] + ba1;
                float gg1 = acc[r][3] + bg1;
                float h0 = a0 * (gg0 * sigmoid_f(gg0));
                float h1v = a1 * (gg1 * sigmoid_f(gg1));
                *(float2*)&C[(size_t)gm * 256 + hc] = make_float2(h0, h1v);
            }
        }
    } else if (EPI == 3) {
        #pragma unroll
        for (int r = 0; r < 8; r++) {
            int gm = bm0 + ty * 8 + r;
            float v[4], ss = 0.0f;
            #pragma unroll
            for (int c = 0; c < 4; c++) {
                float xv = acc[r][c];
                xv = (xv >= 0.0f) ? xv : 0.01f * xv;
                v[c] = xv; ss = fmaf(xv, xv, ss);
            }
            ss += __shfl_xor_sync(0xFFFFFFFFu, ss, 1);
            ss += __shfl_xor_sync(0xFFFFFFFFu, ss, 2);
            float sc = 1.0f / (sqrtf(ss) * 0.25f + 1e-5f);
            #pragma unroll
            for (int c = 0; c < 4; c++) {
                int gn = tx * 4 + c;
                C[(size_t)gm * 64 + gn] = v[c] * sc * p0[gn];
            }
        }
    } else {
        // EPI 4: v = x1 + mg + 0.5*(acc + d1b); C = LN3(v)
        #pragma unroll
        for (int r = 0; r < 8; r++) {
            int gm = bm0 + ty * 8 + r;
            float v[4];
            #pragma unroll
            for (int c = 0; c < 4; c++) {
                int gn = tx * 4 + c;
                size_t ix = (size_t)gm * 64 + gn;
                v[c] = p0[ix] + p1[ix] + 0.5f * (acc[r][c] + p2[gn]);
            }
            float s = half_sum(v[0] + v[1] + v[2] + v[3]);
            float mean = s * (1.0f / 64.0f);
            float d[4], ss = 0.0f;
            #pragma unroll
            for (int c = 0; c < 4; c++) { d[c] = v[c] - mean; ss = fmaf(d[c], d[c], ss); }
            ss = half_sum(ss);
            float inv = rsqrtf(ss * (1.0f / 64.0f) + 1e-5f);
            #pragma unroll
            for (int c = 0; c < 4; c++) {
                int gn = tx * 4 + c;
                C[(size_t)gm * 64 + gn] = d[c] * inv * p3[gn] + p4[gn];
            }
        }
    }
}

// ---------------- fused flash attention (R9 structure + smem bitmask) ----------
// Block: 64-row i-tile for one (b,h). 256 thr = 16 ty (4 rows) x 16 tx (4 j's).
// Mask comes from g_maskbits via an 8KB per-block smem copy (zero mask DRAM in loop).
__global__ void __launch_bounds__(256)
flash_kernel(const float* __restrict__ qkv, const float* __restrict__ relemb,
             float* __restrict__ O) {
    int it = blockIdx.x, bh = blockIdx.y;
    int b = bh >> 2, h = bh & 3;
    int i0 = it * 64;
    __shared__ float qT[16][68];
    __shared__ float kT[16][68];
    __shared__ float vT[16][68];
    __shared__ float relT[16][132];
    __shared__ float osm[64][17];
    __shared__ float rsm[64];
    __shared__ unsigned msk_sh[64 * 32];
    int tid = threadIdx.x, tx = tid & 15, ty = tid >> 4;

    const float* qb = qkv + (size_t)(b * 1024 + i0) * 192 + h * 16;
    for (int f = tid; f < 1024; f += 256) { int r = f >> 4, d = f & 15; qT[d][r] = qb[r * 192 + d]; }
    {
        const unsigned* mb = g_maskbits + ((size_t)bh * 1024 + i0) * 32;
        for (int f = tid; f < 2048; f += 256) msk_sh[f] = mb[f];
    }

    float acc[4][16] = {};
    float rsum[4] = {};
    int lbase = (ty - tx) * 4 + 60;
    int bitb = (tx * 4) & 31;
    int wofs = tx >> 3;            // word offset within the 2-word group per 64-j tile

    for (int jt = 0; jt < 16; jt++) {
        int j0 = jt * 64;
        __syncthreads();   // prev PV done; qT/msk ready on first iter
        const float* kb = qkv + (size_t)(b * 1024 + j0) * 192 + 64 + h * 16;
        for (int f = tid; f < 1024; f += 256) {
            int r = f >> 4, d = f & 15;
            kT[d][r] = kb[r * 192 + d];
            vT[d][r] = kb[r * 192 + 64 + d];
        }
        int pbase = i0 - j0 + 449;
        for (int f = tid; f < 127 * 16; f += 256) {
            int m = f >> 4, d = f & 15;
            int p = min(max(pbase + m, 0), 1024);
            relT[d][m] = relemb[p * 16 + d];
        }
        __syncthreads();

        float s[4][4] = {};
        #pragma unroll
        for (int d = 0; d < 16; d++) {
            float4 aq4 = *(const float4*)&qT[d][ty * 4];
            float4 bk4 = *(const float4*)&kT[d][tx * 4];
            float aq[4] = {aq4.x, aq4.y, aq4.z, aq4.w};
            float bk[4] = {bk4.x, bk4.y, bk4.z, bk4.w};
            float rl[7];
            #pragma unroll
            for (int m = 0; m < 7; m++) rl[m] = relT[d][lbase + m];
            #pragma unroll
            for (int r = 0; r < 4; r++)
                #pragma unroll
                for (int c = 0; c < 4; c++)
                    s[r][c] = fmaf(aq[r], bk[c] + rl[r - c + 3], s[r][c]);
        }

        float e[4][4];
        int wbase = (j0 >> 5) + wofs;
        #pragma unroll
        for (int r = 0; r < 4; r++) {
            unsigned w = msk_sh[(ty * 4 + r) * 32 + wbase];
            e[r][0] = ((w >> (bitb    )) & 1u) ? 0.0f : fast_exp(s[r][0] * 0.25f);
            e[r][1] = ((w >> (bitb + 1)) & 1u) ? 0.0f : fast_exp(s[r][1] * 0.25f);
            e[r][2] = ((w >> (bitb + 2)) & 1u) ? 0.0f : fast_exp(s[r][2] * 0.25f);
            e[r][3] = ((w >> (bitb + 3)) & 1u) ? 0.0f : fast_exp(s[r][3] * 0.25f);
            rsum[r] += e[r][0] + e[r][1] + e[r][2] + e[r][3];
        }

        #pragma unroll
        for (int d = 0; d < 16; d++) {
            float4 v4 = *(const float4*)&vT[d][tx * 4];
            #pragma unroll
            for (int r = 0; r < 4; r++)
                acc[r][d] = fmaf(e[r][0], v4.x,
                            fmaf(e[r][1], v4.y,
                            fmaf(e[r][2], v4.z,
                            fmaf(e[r][3], v4.w, acc[r][d]))));
        }
    }

    #pragma unroll
    for (int r = 0; r < 4; r++) {
        #pragma unroll
        for (int d = 0; d < 16; d++) acc[r][d] = half_sum(acc[r][d]);
        rsum[r] = half_sum(rsum[r]);
    }
    __syncthreads();
    if (tx == 0) {
        #pragma unroll
        for (int r = 0; r < 4; r++) {
            #pragma unroll
            for (int d = 0; d < 16; d++) osm[ty * 4 + r][d] = acc[r][d];
            rsm[ty * 4 + r] = rsum[r];
        }
    }
    __syncthreads();
    for (int f = tid; f < 1024; f += 256) {
        int r = f >> 4, d = f & 15;
        O[(size_t)(b * 1024 + i0 + r) * 64 + h * 16 + d] = osm[r][d] / rsm[r];
    }
}

// ---------------- remaining elementwise stages ----------------
__global__ void convsilu_kernel(const float* __restrict__ convw, const float* __restrict__ convb) {
    int idx = blockIdx.x * blockDim.x + threadIdx.x;
    if (idx >= ROWS * DI) return;
    int d = idx & 127, t = (idx >> 7) & 1023, b = idx >> 17;
    float acc = convb[d];
    #pragma unroll
    for (int k = 0; k < 4; k++) {
        int s = t + k - 3;
        if (s >= 0) acc = fmaf(g_xz[(size_t)((b << 10) + s) * 256 + d], convw[d * 4 + k], acc);
    }
    g_u[idx] = acc * sigmoid_f(acc);
}
__global__ void dtprep_kernel(const float* __restrict__ Wdt, const float* __restrict__ bdt) {
    int idx = blockIdx.x * blockDim.x + threadIdx.x;
    if (idx >= ROWS * DI) return;
    int d = idx & 127, bt = idx >> 7;
    float x = bdt[d];
    #pragma unroll
    for (int r = 0; r < 4; r++) x = fmaf(g_xdb[(size_t)bt * 132 + r], Wdt[r * 128 + d], x);
    g_dt[idx] = (x > 20.0f) ? x : log1pf(fast_exp(x));
}
__global__ void scan_kernel(const float* __restrict__ Alog) {
    int w = (blockIdx.x * blockDim.x + threadIdx.x) >> 5;
    int lane = threadIdx.x & 31;
    int b = w >> 7, d = w & 127;
    float A0 = -__expf(Alog[d * 64 + lane]);
    float A1 = -__expf(Alog[d * 64 + lane + 32]);
    float h0 = 0.0f, h1 = 0.0f;
    const float* dtp = g_dt + (size_t)b * 1024 * 128 + d;
    const float* up  = g_u  + (size_t)b * 1024 * 128 + d;
    const float* xp  = g_xdb + (size_t)b * 1024 * 132;
    float* yp = g_y + (size_t)b * 1024 * 128 + d;
    #pragma unroll 4
    for (int t = 0; t < 1024; t++) {
        float dtv = dtp[t << 7];
        float uv  = up[t << 7];
        float B0 = xp[t * 132 + 4 + lane],  B1 = xp[t * 132 + 36 + lane];
        float C0 = xp[t * 132 + 68 + lane], C1 = xp[t * 132 + 100 + lane];
        float du = dtv * uv;
        h0 = fmaf(h0, __expf(dtv * A0), du * B0);
        h1 = fmaf(h1, __expf(dtv * A1), du * B1);
        float p = fmaf(h0, C0, h1 * C1);
        p = warp_sum(p);
        if (lane == 0) yp[t << 7] = p;
    }
}

// ---------------- launch ----------------
static void* dev_ptr(const void* sym) { void* p = nullptr; cudaGetSymbolAddress(&p, sym); return p; }

extern "C" void kernel_launch(void* const* d_in, const int* in_sizes, int n_in,
                              void* d_out, int out_size) {
    const float* x      = (const float*)d_in[0];
    const void*  dmask  = d_in[1];
    const float* ln1w   = (const float*)d_in[2];
    const float* ln1b   = (const float*)d_in[3];
    const float* Wq     = (const float*)d_in[4];
    const float* Wkv    = (const float*)d_in[5];
    const float* Wo     = (const float*)d_in[6];
    const float* bo     = (const float*)d_in[7];
    const float* relemb = (const float*)d_in[8];
    const float* ln2w   = (const float*)d_in[9];
    const float* ln2b   = (const float*)d_in[10];
    const float* Win    = (const float*)d_in[11];
    const float* convw  = (const float*)d_in[12];
    const float* convb  = (const float*)d_in[13];
    const float* Wxproj = (const float*)d_in[14];
    const float* Wdt    = (const float*)d_in[15];
    const float* bdt    = (const float*)d_in[16];
    const float* Alog   = (const float*)d_in[17];
    const float* Dm     = (const float*)d_in[18];
    const float* Wout   = (const float*)d_in[19];
    const float* gamma  = (const float*)d_in[20];
    const float* c1w    = (const float*)d_in[21];
    const float* c1b    = (const float*)d_in[22];
    const float* d1w    = (const float*)d_in[23];
    const float* d1b    = (const float*)d_in[24];
    const float* ln3w   = (const float*)d_in[25];
    const float* ln3b   = (const float*)d_in[26];
    float* out = (float*)d_out;

    float* p_xt    = (float*)dev_ptr(g_xt);
    float* p_wqkv  = (float*)dev_ptr(g_wqkv);
    float* p_qkv   = (float*)dev_ptr(g_qkv);
    float* p_O     = (float*)dev_ptr(g_O);
    float* p_x1    = (float*)dev_ptr(g_x1);
    float* p_xt2   = (float*)dev_ptr(g_xt2);
    float* p_xz    = (float*)dev_ptr(g_xz);
    float* p_u     = (float*)dev_ptr(g_u);
    float* p_xdb   = (float*)dev_ptr(g_xdb);
    float* p_y     = (float*)dev_ptr(g_y);
    float* p_mg    = (float*)dev_ptr(g_mg);
    float* p_B1    = (float*)dev_ptr(g_B1);
    float* p_c1bp  = (float*)dev_ptr(g_c1bp);
    float* p_h1    = (float*)dev_ptr(g_h1);
    float* p_B2    = (float*)dev_ptr(g_B2);

    // 0: mask sniff + all weight rearrangement (one launch), then bit-compress mask
    int build_elems = 64*192 + 256*512 + 1024*64 + 512;
    init_kernel<<<1 + (build_elems + 255) / 256, 256>>>(
        (const unsigned int*)dmask, Wq, Wkv, c1w, d1w, c1b);
    maskbits_kernel<<<4096, 256>>>(dmask);   // 32768 warps x 32 words

    // 1: LN1 + QKV projection
    ln_kernel<<<1024, 256>>>(x, ln1w, ln1b, p_xt, ROWS);
    gemm128t<0,0><<<dim3(3, 64), 256>>>(p_xt, p_wqkv, p_qkv, ROWS, 192, 64,
                                        nullptr, nullptr, nullptr, nullptr, nullptr, nullptr);

    // 2: fused flash attention (bitmask from smem)
    flash_kernel<<<dim3(16, BH), 256>>>(p_qkv, relemb, p_O);

    // 3: Wo proj + bias + double residual + LN2 (one kernel) -> g_x1, g_xt2
    gemm128t<0,1><<<dim3(1, 64), 256>>>(p_O, Wo, p_x1, ROWS, 64, 64,
                                        x, bo, ln2w, ln2b, nullptr, p_xt2);

    // 4: Mamba
    gemm128t<0,0><<<dim3(4, 64), 256>>>(p_xt2, Win, p_xz, ROWS, 256, 64,
                                        nullptr, nullptr, nullptr, nullptr, nullptr, nullptr);
    convsilu_kernel<<<(ROWS * DI + 255) / 256, 256>>>(convw, convb);
    gemm128t<0,0><<<dim3(3, 64), 256>>>(p_u, Wxproj, p_xdb, ROWS, 132, DI,
                                        nullptr, nullptr, nullptr, nullptr, nullptr, nullptr);
    dtprep_kernel<<<(ROWS * DI + 255) / 256, 256>>>(Wdt, bdt);
    scan_kernel<<<128, 256>>>(Alog);
    // Wout: on-the-fly ym (amode3) + leaky+groupRMS (epi3) -> g_mg
    gemm128t<3,3><<<dim3(1, 64), 256>>>(p_y, Wout, p_mg, ROWS, 64, DI,
                                        gamma, p_u, p_xz, Dm, nullptr, nullptr);

    // 5: FF — conv1 (implicit im2col + gated epilogue) -> h1
    gemm128t<1,2><<<dim3(8, 65), 256>>>(p_mg, p_B1, p_h1, ROWS1, 512, 256,
                                        p_c1bp, nullptr, nullptr, nullptr, nullptr, nullptr);
    //    conv2 + final residual + LN3 -> out
    gemm128t<2,4><<<dim3(1, 64), 256>>>(p_h1, p_B2, out, ROWS, 64, 1024,
                                        p_x1, p_mg, d1b, ln3w, ln3b, nullptr);

    (void)in_sizes; (void)n_in; (void)out_size;
}

// round 15
// speedup vs baseline: 1.2424x; 1.0170x over previous
#include <cuda_runtime.h>
#include <mma.h>
#include <cstdint>
#include <cstdio>

using namespace nvcuda;

// ---------------- problem dims ----------------
#define B8    8
#define N1    1024
#define DD    64
#define HH    4
#define DHH   16
#define DI    128
#define DS    64
#define ROWS  (B8*N1)          // 8192
#define BH    (B8*HH)          // 32
#define T1    1027             // conv1 output length
#define ROWS1 (B8*T1)          // 8216

// ---------------- scratch (static device globals; no allocation) ----------------
__device__ float g_xt   [ROWS*DD];
__device__ float g_wqkv [64*192];
__device__ float g_qkv  [ROWS*192];
__device__ float g_O    [ROWS*DD];
__device__ float g_x1   [ROWS*DD];
__device__ float g_xt2  [ROWS*DD];
__device__ float g_xz   [ROWS*256];
__device__ float g_u    [ROWS*DI];
__device__ float g_xdb  [ROWS*132];
__device__ float g_dt   [ROWS*DI];
__device__ float g_y    [ROWS*DI];
__device__ float g_mg   [ROWS*DD];
__device__ float g_B1   [256*512];      // interleaved (a,gate) columns
__device__ float g_c1bp [512];          // permuted conv1 bias
__device__ float g_h1   [ROWS1*256];
__device__ float g_B2   [1024*64];
__device__ unsigned g_maskbits[BH*N1*32];   // 1 bit per (bh,i,j); 32 words per row
__device__ int   g_mask_mode;

// ---------------- helpers ----------------
__device__ __forceinline__ float fast_exp(float x) {
    float t = x * 1.4426950408889634f;
    t = fminf(fmaxf(t, -126.0f), 126.0f);
    float fi = floorf(t);
    float f  = t - fi;
    float p = 0.0018775767f;
    p = fmaf(p, f, 0.0089893397f);
    p = fmaf(p, f, 0.055826318f);
    p = fmaf(p, f, 0.24015361f);
    p = fmaf(p, f, 0.69315308f);
    p = fmaf(p, f, 0.99999994f);
    return p * __int_as_float(((int)fi + 127) << 23);
}
__device__ __forceinline__ float sigmoid_f(float x) { return 1.0f / (1.0f + fast_exp(-x)); }
__device__ __forceinline__ float warp_sum(float v) {
    #pragma unroll
    for (int o = 16; o > 0; o >>= 1) v += __shfl_xor_sync(0xFFFFFFFFu, v, o);
    return v;
}
__device__ __forceinline__ float half_sum(float v) {   // reduce over 16-lane group
    v += __shfl_xor_sync(0xFFFFFFFFu, v, 1);
    v += __shfl_xor_sync(0xFFFFFFFFu, v, 2);
    v += __shfl_xor_sync(0xFFFFFFFFu, v, 4);
    v += __shfl_xor_sync(0xFFFFFFFFu, v, 8);
    return v;
}

// ---------------- init: mask sniff (block 0) + weight builders ----------------
__global__ void init_kernel(const unsigned int* __restrict__ m,
                            const float* __restrict__ Wq, const float* __restrict__ Wkv,
                            const float* __restrict__ c1w, const float* __restrict__ d1w,
                            const float* __restrict__ c1b) {
    if (blockIdx.x == 0) {
        __shared__ int cf, co;
        if (threadIdx.x == 0) { cf = 0; co = 0; }
        __syncthreads();
        int lf = 0, lo = 0;
        for (int k = 0; k < 16; k++) {
            unsigned w = m[threadIdx.x + k * 256];
            if (w == 0x3F800000u) lf++;
            else if (w != 0u && w != 1u) lo++;
        }
        atomicAdd(&cf, lf); atomicAdd(&co, lo);
        __syncthreads();
        if (threadIdx.x == 0)
            g_mask_mode = (cf > 32) ? 0 : ((co > 32) ? 2 : 1);
        return;
    }
    int idx = (blockIdx.x - 1) * 256 + threadIdx.x;
    if (idx < 64 * 192) {
        int k = idx / 192, c = idx % 192;
        g_wqkv[idx] = (c < 64) ? Wq[k * 64 + c] : Wkv[k * 128 + (c - 64)];
        return;
    }
    int i1 = idx - 64 * 192;
    if (i1 < 256 * 512) {
        int r = i1 >> 9, c = i1 & 511;
        int k = c >> 1, half = c & 1;
        int o = k + half * 256;
        int kt = r >> 6, ci = r & 63;
        g_B1[i1] = c1w[o * 256 + ci * 4 + kt];
        return;
    }
    int i2 = i1 - 256 * 512;
    if (i2 < 1024 * 64) {
        int r = i2 >> 6, co2 = i2 & 63;
        int ci = r >> 2, j = r & 3;
        g_B2[i2] = d1w[ci * 256 + co2 * 4 + j];
        return;
    }
    int i3 = i2 - 1024 * 64;
    if (i3 < 512) g_c1bp[i3] = c1b[(i3 >> 1) + (i3 & 1) * 256];
}

// ---------------- mask -> bitmask (perfectly coalesced ballot stream) ----------
__global__ void maskbits_kernel(const void* __restrict__ mask) {
    int warp = (blockIdx.x * blockDim.x + threadIdx.x) >> 5;
    int lane = threadIdx.x & 31;
    int mode = g_mask_mode;
    size_t ebase = (size_t)warp * 1024;
    #pragma unroll 4
    for (int k = 0; k < 32; k++) {
        size_t e = ebase + (size_t)k * 32 + lane;
        bool bit;
        if (mode == 0)      bit = ((const float*)mask)[e] != 0.0f;
        else if (mode == 1) bit = ((const int*)mask)[e] != 0;
        else                bit = ((const unsigned char*)mask)[e] != 0;
        unsigned w = __ballot_sync(0xFFFFFFFFu, bit);
        if (lane == 0) g_maskbits[warp * 32 + k] = w;
    }
}

// ---------------- layernorm (warp per row of 64) ----------------
__global__ void ln_kernel(const float* __restrict__ x, const float* __restrict__ w,
                          const float* __restrict__ b, float* __restrict__ out, int rows) {
    int warp = (blockIdx.x * blockDim.x + threadIdx.x) >> 5;
    int lane = threadIdx.x & 31;
    if (warp >= rows) return;
    const float* xr = x + (size_t)warp * 64;
    float v0 = xr[lane], v1 = xr[lane + 32];
    float mean = warp_sum(v0 + v1) * (1.0f / 64.0f);
    float d0 = v0 - mean, d1 = v1 - mean;
    float var = warp_sum(d0 * d0 + d1 * d1) * (1.0f / 64.0f);
    float inv = rsqrtf(var + 1e-5f);
    float* orow = out + (size_t)warp * 64;
    orow[lane]      = d0 * inv * w[lane]      + b[lane];
    orow[lane + 32] = d1 * inv * w[lane + 32] + b[lane + 32];
}

// ---------------- templated GEMM: 128x64 tile, 8x4 micro, double-buffered smem
// AMODE 0: A row-major [M,K]
// AMODE 2: conv2 implicit im2col from g_h1 (A)
// AMODE 3: A = (y + u*Dm)*silu(z) on-the-fly (A=g_y, p1=u, p2=xz, p3=Dm)
// EPI 0: C = acc (bounds-checked)
// EPI 1: x1 = 2*p0 + acc + p1[col]; C=x1; q0 = LN(x1; p2,p3)
// EPI 3: leaky + group-RMS(16): p0 = gamma
// EPI 4: v = p0 + p1 + 0.5*(acc + p2[col]); C = LN(v; p3,p4)
template<int AMODE, int EPI>
__global__ void __launch_bounds__(256, 2)
gemm128t(const float* __restrict__ A, const float* __restrict__ B,
         float* __restrict__ C, int M, int N, int K,
         const float* __restrict__ p0, const float* __restrict__ p1,
         const float* __restrict__ p2, const float* __restrict__ p3,
         const float* __restrict__ p4, float* __restrict__ q0) {
    __shared__ float As[2][16][132];
    __shared__ float Bs[2][16][68];
    int bm0 = blockIdx.y * 128, bn0 = blockIdx.x * 64;
    int tid = threadIdx.x;
    int tx = tid & 15, ty = tid >> 4;

    size_t abase[8];
    int    aaux[8];
    bool   avalid[8];
    #pragma unroll
    for (int i = 0; i < 8; i++) {
        int f = tid + i * 256;
        int gm = bm0 + (f >> 4);
        avalid[i] = (gm < M);
        int gmc = avalid[i] ? gm : 0;
        if (AMODE == 0) {
            abase[i] = (size_t)gmc * K; aaux[i] = 0;
        } else if (AMODE == 2) {
            int b = gmc >> 10, s = gmc & 1023;
            abase[i] = ((size_t)b * 1027 + s) * 256; aaux[i] = 0;
        } else {
            abase[i] = (size_t)gmc * 128; aaux[i] = gmc * 256 + 128;
        }
    }

    float ra[8], rb[4];
    auto fetch = [&](int k0) {
        #pragma unroll
        for (int i = 0; i < 8; i++) {
            int f = tid + i * 256;
            int kk = f & 15;
            int k = k0 + kk;
            float v = 0.0f;
            if (AMODE == 0) {
                if (avalid[i]) v = A[abase[i] + k];
            } else if (AMODE == 2) {
                int ci = k >> 2, j = k & 3;
                if (avalid[i]) v = A[abase[i] + (size_t)(3 - j) * 256 + ci];
            } else {
                if (avalid[i]) {
                    float y  = A[abase[i] + k];
                    float uu = p1[abase[i] + k];
                    float z  = p2[aaux[i] + k];
                    v = (y + uu * p3[k]) * (z * sigmoid_f(z));
                }
            }
            ra[i] = v;
        }
        #pragma unroll
        for (int i = 0; i < 4; i++) {
            int f = tid + i * 256;
            int kk = f >> 6, n = f & 63;
            int gn = bn0 + n;
            rb[i] = (gn < N) ? B[(size_t)(k0 + kk) * N + gn] : 0.0f;
        }
    };
    auto stage = [&](int buf) {
        #pragma unroll
        for (int i = 0; i < 8; i++) {
            int f = tid + i * 256;
            As[buf][f & 15][f >> 4] = ra[i];
        }
        #pragma unroll
        for (int i = 0; i < 4; i++) {
            int f = tid + i * 256;
            Bs[buf][f >> 6][f & 63] = rb[i];
        }
    };

    fetch(0);
    stage(0);
    __syncthreads();

    float acc[8][4] = {};
    int T = K >> 4;
    for (int t = 0; t < T; t++) {
        int buf = t & 1;
        if (t + 1 < T) fetch((t + 1) << 4);
        #pragma unroll
        for (int kk = 0; kk < 16; kk++) {
            float4 a0 = *(const float4*)&As[buf][kk][ty * 8];
            float4 a1 = *(const float4*)&As[buf][kk][ty * 8 + 4];
            float4 b4 = *(const float4*)&Bs[buf][kk][tx * 4];
            float av[8] = {a0.x, a0.y, a0.z, a0.w, a1.x, a1.y, a1.z, a1.w};
            float bv[4] = {b4.x, b4.y, b4.z, b4.w};
            #pragma unroll
            for (int r = 0; r < 8; r++)
                #pragma unroll
                for (int c = 0; c < 4; c++)
                    acc[r][c] = fmaf(av[r], bv[c], acc[r][c]);
        }
        if (t + 1 < T) stage(buf ^ 1);
        __syncthreads();
    }

    if (EPI == 0) {
        #pragma unroll
        for (int r = 0; r < 8; r++) {
            int gm = bm0 + ty * 8 + r;
            if (gm < M) {
                #pragma unroll
                for (int c = 0; c < 4; c++) {
                    int gn = bn0 + tx * 4 + c;
                    if (gn < N) C[(size_t)gm * N + gn] = acc[r][c];
                }
            }
        }
    } else if (EPI == 1) {
        #pragma unroll
        for (int r = 0; r < 8; r++) {
            int gm = bm0 + ty * 8 + r;
            float v[4];
            #pragma unroll
            for (int c = 0; c < 4; c++) {
                int gn = tx * 4 + c;
                v[c] = 2.0f * p0[(size_t)gm * 64 + gn] + acc[r][c] + p1[gn];
                C[(size_t)gm * 64 + gn] = v[c];
            }
            float s = half_sum(v[0] + v[1] + v[2] + v[3]);
            float mean = s * (1.0f / 64.0f);
            float d[4], ss = 0.0f;
            #pragma unroll
            for (int c = 0; c < 4; c++) { d[c] = v[c] - mean; ss = fmaf(d[c], d[c], ss); }
            ss = half_sum(ss);
            float inv = rsqrtf(ss * (1.0f / 64.0f) + 1e-5f);
            #pragma unroll
            for (int c = 0; c < 4; c++) {
                int gn = tx * 4 + c;
                q0[(size_t)gm * 64 + gn] = d[c] * inv * p2[gn] + p3[gn];
            }
        }
    } else if (EPI == 3) {
        #pragma unroll
        for (int r = 0; r < 8; r++) {
            int gm = bm0 + ty * 8 + r;
            float v[4], ss = 0.0f;
            #pragma unroll
            for (int c = 0; c < 4; c++) {
                float xv = acc[r][c];
                xv = (xv >= 0.0f) ? xv : 0.01f * xv;
                v[c] = xv; ss = fmaf(xv, xv, ss);
            }
            ss += __shfl_xor_sync(0xFFFFFFFFu, ss, 1);
            ss += __shfl_xor_sync(0xFFFFFFFFu, ss, 2);
            float sc = 1.0f / (sqrtf(ss) * 0.25f + 1e-5f);
            #pragma unroll
            for (int c = 0; c < 4; c++) {
                int gn = tx * 4 + c;
                C[(size_t)gm * 64 + gn] = v[c] * sc * p0[gn];
            }
        }
    } else {
        // EPI 4: v = x1 + mg + 0.5*(acc + d1b); C = LN3(v)
        #pragma unroll
        for (int r = 0; r < 8; r++) {
            int gm = bm0 + ty * 8 + r;
            float v[4];
            #pragma unroll
            for (int c = 0; c < 4; c++) {
                int gn = tx * 4 + c;
                size_t ix = (size_t)gm * 64 + gn;
                v[c] = p0[ix] + p1[ix] + 0.5f * (acc[r][c] + p2[gn]);
            }
            float s = half_sum(v[0] + v[1] + v[2] + v[3]);
            float mean = s * (1.0f / 64.0f);
            float d[4], ss = 0.0f;
            #pragma unroll
            for (int c = 0; c < 4; c++) { d[c] = v[c] - mean; ss = fmaf(d[c], d[c], ss); }
            ss = half_sum(ss);
            float inv = rsqrtf(ss * (1.0f / 64.0f) + 1e-5f);
            #pragma unroll
            for (int c = 0; c < 4; c++) {
                int gn = tx * 4 + c;
                C[(size_t)gm * 64 + gn] = d[c] * inv * p3[gn] + p4[gn];
            }
        }
    }
}

// ---------------- conv1 via tf32 wmma tensor cores ---------------------------
// C[ROWS1, 512] = im2col(g_mg) @ g_B1, gated epilogue -> g_h1[ROWS1, 256]
// Block 128(M) x 64(N), 8 warps as 4(M) x 2(N), warp = 2x2 wmma(16,16,8) tiles.
__global__ void __launch_bounds__(256)
conv1_wmma_kernel(const float* __restrict__ mg, const float* __restrict__ B1,
                  const float* __restrict__ c1bp, float* __restrict__ h1) {
    __shared__ float sm[128 * 68];          // 34.8KB; staged As+Bs, reused as Co
    float* As = sm;                          // [128][20]
    float* Bs = sm + 128 * 20;               // [16][68]
    float* Co = sm;                          // [128][68] epilogue reuse

    int bn0 = blockIdx.x * 64;               // B1 column base (0..448)
    int bm0 = blockIdx.y * 128;
    int tid = threadIdx.x;
    int wid = tid >> 5;
    int warp_m = wid & 3, warp_n = wid >> 2;

    int arow_t[8]; int abase[8]; bool avalid[8];
    #pragma unroll
    for (int i = 0; i < 8; i++) {
        int f = tid + i * 256;
        int gm = bm0 + (f >> 4);
        avalid[i] = (gm < ROWS1);
        int gmc = avalid[i] ? gm : 0;
        int b = gmc / 1027;
        arow_t[i] = gmc - b * 1027;
        abase[i] = (b << 10) * 64;
    }

    wmma::fragment<wmma::accumulator, 16, 16, 8, float> c[2][2];
    #pragma unroll
    for (int mi = 0; mi < 2; mi++)
        #pragma unroll
        for (int ni = 0; ni < 2; ni++)
            wmma::fill_fragment(c[mi][ni], 0.0f);

    for (int k0 = 0; k0 < 256; k0 += 16) {
        #pragma unroll
        for (int i = 0; i < 8; i++) {
            int f = tid + i * 256;
            int m = f >> 4, kk = f & 15;
            int k = k0 + kk;
            int kt = k >> 6, ci = k & 63;
            int s = arow_t[i] + kt - 3;
            float v = 0.0f;
            if (avalid[i] && s >= 0 && s < 1024) v = mg[abase[i] + s * 64 + ci];
            As[m * 20 + kk] = v;
        }
        #pragma unroll
        for (int i = 0; i < 4; i++) {
            int f = tid + i * 256;
            int kk = f >> 6, n = f & 63;
            Bs[kk * 68 + n] = B1[(k0 + kk) * 512 + bn0 + n];
        }
        __syncthreads();
        #pragma unroll
        for (int ks = 0; ks < 16; ks += 8) {
            wmma::fragment<wmma::matrix_a, 16, 16, 8, wmma::precision::tf32, wmma::row_major> a[2];
            wmma::fragment<wmma::matrix_b, 16, 16, 8, wmma::precision::tf32, wmma::row_major> bf[2];
            #pragma unroll
            for (int mi = 0; mi < 2; mi++) {
                wmma::load_matrix_sync(a[mi], &As[(warp_m * 32 + mi * 16) * 20 + ks], 20);
                #pragma unroll
                for (int t = 0; t < a[mi].num_elements; t++)
                    a[mi].x[t] = wmma::__float_to_tf32(a[mi].x[t]);
            }
            #pragma unroll
            for (int ni = 0; ni < 2; ni++) {
                wmma::load_matrix_sync(bf[ni], &Bs[ks * 68 + warp_n * 32 + ni * 16], 68);
                #pragma unroll
                for (int t = 0; t < bf[ni].num_elements; t++)
                    bf[ni].x[t] = wmma::__float_to_tf32(bf[ni].x[t]);
            }
            #pragma unroll
            for (int mi = 0; mi < 2; mi++)
                #pragma unroll
                for (int ni = 0; ni < 2; ni++)
                    wmma::mma_sync(c[mi][ni], a[mi], bf[ni], c[mi][ni]);
        }
        __syncthreads();
    }

    // epilogue: acc -> smem -> gated combine -> h1
    #pragma unroll
    for (int mi = 0; mi < 2; mi++)
        #pragma unroll
        for (int ni = 0; ni < 2; ni++)
            wmma::store_matrix_sync(&Co[(warp_m * 32 + mi * 16) * 68 + warp_n * 32 + ni * 16],
                                    c[mi][ni], 68, wmma::mem_row_major);
    __syncthreads();
    int hbase = bn0 >> 1;
    for (int f = tid; f < 128 * 32; f += 256) {
        int m = f >> 5, hc = f & 31;
        int gm = bm0 + m;
        if (gm < ROWS1) {
            float a = Co[m * 68 + hc * 2]     + c1bp[bn0 + hc * 2];
            float g = Co[m * 68 + hc * 2 + 1] + c1bp[bn0 + hc * 2 + 1];
            h1[(size_t)gm * 256 + hbase + hc] = a * (g * sigmoid_f(g));
        }
    }
}

// ---------------- fused flash attention (R9 structure + smem bitmask) ----------
__global__ void __launch_bounds__(256)
flash_kernel(const float* __restrict__ qkv, const float* __restrict__ relemb,
             float* __restrict__ O) {
    int it = blockIdx.x, bh = blockIdx.y;
    int b = bh >> 2, h = bh & 3;
    int i0 = it * 64;
    __shared__ float qT[16][68];
    __shared__ float kT[16][68];
    __shared__ float vT[16][68];
    __shared__ float relT[16][132];
    __shared__ float osm[64][17];
    __shared__ float rsm[64];
    __shared__ unsigned msk_sh[64 * 32];
    int tid = threadIdx.x, tx = tid & 15, ty = tid >> 4;

    const float* qb = qkv + (size_t)(b * 1024 + i0) * 192 + h * 16;
    for (int f = tid; f < 1024; f += 256) { int r = f >> 4, d = f & 15; qT[d][r] = qb[r * 192 + d]; }
    {
        const unsigned* mb = g_maskbits + ((size_t)bh * 1024 + i0) * 32;
        for (int f = tid; f < 2048; f += 256) msk_sh[f] = mb[f];
    }

    float acc[4][16] = {};
    float rsum[4] = {};
    int lbase = (ty - tx) * 4 + 60;
    int bitb = (tx * 4) & 31;
    int wofs = tx >> 3;

    for (int jt = 0; jt < 16; jt++) {
        int j0 = jt * 64;
        __syncthreads();
        const float* kb = qkv + (size_t)(b * 1024 + j0) * 192 + 64 + h * 16;
        for (int f = tid; f < 1024; f += 256) {
            int r = f >> 4, d = f & 15;
            kT[d][r] = kb[r * 192 + d];
            vT[d][r] = kb[r * 192 + 64 + d];
        }
        int pbase = i0 - j0 + 449;
        for (int f = tid; f < 127 * 16; f += 256) {
            int m = f >> 4, d = f & 15;
            int p = min(max(pbase + m, 0), 1024);
            relT[d][m] = relemb[p * 16 + d];
        }
        __syncthreads();

        float s[4][4] = {};
        #pragma unroll
        for (int d = 0; d < 16; d++) {
            float4 aq4 = *(const float4*)&qT[d][ty * 4];
            float4 bk4 = *(const float4*)&kT[d][tx * 4];
            float aq[4] = {aq4.x, aq4.y, aq4.z, aq4.w};
            float bk[4] = {bk4.x, bk4.y, bk4.z, bk4.w};
            float rl[7];
            #pragma unroll
            for (int m = 0; m < 7; m++) rl[m] = relT[d][lbase + m];
            #pragma unroll
            for (int r = 0; r < 4; r++)
                #pragma unroll
                for (int c = 0; c < 4; c++)
                    s[r][c] = fmaf(aq[r], bk[c] + rl[r - c + 3], s[r][c]);
        }

        float e[4][4];
        int wbase = (j0 >> 5) + wofs;
        #pragma unroll
        for (int r = 0; r < 4; r++) {
            unsigned w = msk_sh[(ty * 4 + r) * 32 + wbase];
            e[r][0] = ((w >> (bitb    )) & 1u) ? 0.0f : fast_exp(s[r][0] * 0.25f);
            e[r][1] = ((w >> (bitb + 1)) & 1u) ? 0.0f : fast_exp(s[r][1] * 0.25f);
            e[r][2] = ((w >> (bitb + 2)) & 1u) ? 0.0f : fast_exp(s[r][2] * 0.25f);
            e[r][3] = ((w >> (bitb + 3)) & 1u) ? 0.0f : fast_exp(s[r][3] * 0.25f);
            rsum[r] += e[r][0] + e[r][1] + e[r][2] + e[r][3];
        }

        #pragma unroll
        for (int d = 0; d < 16; d++) {
            float4 v4 = *(const float4*)&vT[d][tx * 4];
            #pragma unroll
            for (int r = 0; r < 4; r++)
                acc[r][d] = fmaf(e[r][0], v4.x,
                            fmaf(e[r][1], v4.y,
                            fmaf(e[r][2], v4.z,
                            fmaf(e[r][3], v4.w, acc[r][d]))));
        }
    }

    #pragma unroll
    for (int r = 0; r < 4; r++) {
        #pragma unroll
        for (int d = 0; d < 16; d++) acc[r][d] = half_sum(acc[r][d]);
        rsum[r] = half_sum(rsum[r]);
    }
    __syncthreads();
    if (tx == 0) {
        #pragma unroll
        for (int r = 0; r < 4; r++) {
            #pragma unroll
            for (int d = 0; d < 16; d++) osm[ty * 4 + r][d] = acc[r][d];
            rsm[ty * 4 + r] = rsum[r];
        }
    }
    __syncthreads();
    for (int f = tid; f < 1024; f += 256) {
        int r = f >> 4, d = f & 15;
        O[(size_t)(b * 1024 + i0 + r) * 64 + h * 16 + d] = osm[r][d] / rsm[r];
    }
}

// ---------------- remaining elementwise stages ----------------
__global__ void convsilu_kernel(const float* __restrict__ convw, const float* __restrict__ convb) {
    int idx = blockIdx.x * blockDim.x + threadIdx.x;
    if (idx >= ROWS * DI) return;
    int d = idx & 127, t = (idx >> 7) & 1023, b = idx >> 17;
    float acc = convb[d];
    #pragma unroll
    for (int k = 0; k < 4; k++) {
        int s = t + k - 3;
        if (s >= 0) acc = fmaf(g_xz[(size_t)((b << 10) + s) * 256 + d], convw[d * 4 + k], acc);
    }
    g_u[idx] = acc * sigmoid_f(acc);
}
__global__ void dtprep_kernel(const float* __restrict__ Wdt, const float* __restrict__ bdt) {
    int idx = blockIdx.x * blockDim.x + threadIdx.x;
    if (idx >= ROWS * DI) return;
    int d = idx & 127, bt = idx >> 7;
    float x = bdt[d];
    #pragma unroll
    for (int r = 0; r < 4; r++) x = fmaf(g_xdb[(size_t)bt * 132 + r], Wdt[r * 128 + d], x);
    g_dt[idx] = (x > 20.0f) ? x : log1pf(fast_exp(x));
}
__global__ void scan_kernel(const float* __restrict__ Alog) {
    int w = (blockIdx.x * blockDim.x + threadIdx.x) >> 5;
    int lane = threadIdx.x & 31;
    int b = w >> 7, d = w & 127;
    float A0 = -__expf(Alog[d * 64 + lane]);
    float A1 = -__expf(Alog[d * 64 + lane + 32]);
    float h0 = 0.0f, h1 = 0.0f;
    const float* dtp = g_dt + (size_t)b * 1024 * 128 + d;
    const float* up  = g_u  + (size_t)b * 1024 * 128 + d;
    const float* xp  = g_xdb + (size_t)b * 1024 * 132;
    float* yp = g_y + (size_t)b * 1024 * 128 + d;
    #pragma unroll 4
    for (int t = 0; t < 1024; t++) {
        float dtv = dtp[t << 7];
        float uv  = up[t << 7];
        float B0 = xp[t * 132 + 4 + lane],  B1 = xp[t * 132 + 36 + lane];
        float C0 = xp[t * 132 + 68 + lane], C1 = xp[t * 132 + 100 + lane];
        float du = dtv * uv;
        h0 = fmaf(h0, __expf(dtv * A0), du * B0);
        h1 = fmaf(h1, __expf(dtv * A1), du * B1);
        float p = fmaf(h0, C0, h1 * C1);
        p = warp_sum(p);
        if (lane == 0) yp[t << 7] = p;
    }
}

// ---------------- launch ----------------
static void* dev_ptr(const void* sym) { void* p = nullptr; cudaGetSymbolAddress(&p, sym); return p; }

extern "C" void kernel_launch(void* const* d_in, const int* in_sizes, int n_in,
                              void* d_out, int out_size) {
    const float* x      = (const float*)d_in[0];
    const void*  dmask  = d_in[1];
    const float* ln1w   = (const float*)d_in[2];
    const float* ln1b   = (const float*)d_in[3];
    const float* Wq     = (const float*)d_in[4];
    const float* Wkv    = (const float*)d_in[5];
    const float* Wo     = (const float*)d_in[6];
    const float* bo     = (const float*)d_in[7];
    const float* relemb = (const float*)d_in[8];
    const float* ln2w   = (const float*)d_in[9];
    const float* ln2b   = (const float*)d_in[10];
    const float* Win    = (const float*)d_in[11];
    const float* convw  = (const float*)d_in[12];
    const float* convb  = (const float*)d_in[13];
    const float* Wxproj = (const float*)d_in[14];
    const float* Wdt    = (const float*)d_in[15];
    const float* bdt    = (const float*)d_in[16];
    const float* Alog   = (const float*)d_in[17];
    const float* Dm     = (const float*)d_in[18];
    const float* Wout   = (const float*)d_in[19];
    const float* gamma  = (const float*)d_in[20];
    const float* c1w    = (const float*)d_in[21];
    const float* c1b    = (const float*)d_in[22];
    const float* d1w    = (const float*)d_in[23];
    const float* d1b    = (const float*)d_in[24];
    const float* ln3w   = (const float*)d_in[25];
    const float* ln3b   = (const float*)d_in[26];
    float* out = (float*)d_out;

    float* p_xt    = (float*)dev_ptr(g_xt);
    float* p_wqkv  = (float*)dev_ptr(g_wqkv);
    float* p_qkv   = (float*)dev_ptr(g_qkv);
    float* p_O     = (float*)dev_ptr(g_O);
    float* p_x1    = (float*)dev_ptr(g_x1);
    float* p_xt2   = (float*)dev_ptr(g_xt2);
    float* p_xz    = (float*)dev_ptr(g_xz);
    float* p_u     = (float*)dev_ptr(g_u);
    float* p_xdb   = (float*)dev_ptr(g_xdb);
    float* p_y     = (float*)dev_ptr(g_y);
    float* p_mg    = (float*)dev_ptr(g_mg);
    float* p_B1    = (float*)dev_ptr(g_B1);
    float* p_c1bp  = (float*)dev_ptr(g_c1bp);
    float* p_h1    = (float*)dev_ptr(g_h1);
    float* p_B2    = (float*)dev_ptr(g_B2);

    // 0: mask sniff + weight rearrangement, then bit-compress mask
    int build_elems = 64*192 + 256*512 + 1024*64 + 512;
    init_kernel<<<1 + (build_elems + 255) / 256, 256>>>(
        (const unsigned int*)dmask, Wq, Wkv, c1w, d1w, c1b);
    maskbits_kernel<<<4096, 256>>>(dmask);

    // 1: LN1 + QKV projection
    ln_kernel<<<1024, 256>>>(x, ln1w, ln1b, p_xt, ROWS);
    gemm128t<0,0><<<dim3(3, 64), 256>>>(p_xt, p_wqkv, p_qkv, ROWS, 192, 64,
                                        nullptr, nullptr, nullptr, nullptr, nullptr, nullptr);

    // 2: fused flash attention (bitmask from smem)
    flash_kernel<<<dim3(16, BH), 256>>>(p_qkv, relemb, p_O);

    // 3: Wo proj + bias + double residual + LN2 -> g_x1, g_xt2
    gemm128t<0,1><<<dim3(1, 64), 256>>>(p_O, Wo, p_x1, ROWS, 64, 64,
                                        x, bo, ln2w, ln2b, nullptr, p_xt2);

    // 4: Mamba
    gemm128t<0,0><<<dim3(4, 64), 256>>>(p_xt2, Win, p_xz, ROWS, 256, 64,
                                        nullptr, nullptr, nullptr, nullptr, nullptr, nullptr);
    convsilu_kernel<<<(ROWS * DI + 255) / 256, 256>>>(convw, convb);
    gemm128t<0,0><<<dim3(3, 64), 256>>>(p_u, Wxproj, p_xdb, ROWS, 132, DI,
                                        nullptr, nullptr, nullptr, nullptr, nullptr, nullptr);
    dtprep_kernel<<<(ROWS * DI + 255) / 256, 256>>>(Wdt, bdt);
    scan_kernel<<<128, 256>>>(Alog);
    // Wout: on-the-fly ym (amode3) + leaky+groupRMS (epi3) -> g_mg
    gemm128t<3,3><<<dim3(1, 64), 256>>>(p_y, Wout, p_mg, ROWS, 64, DI,
                                        gamma, p_u, p_xz, Dm, nullptr, nullptr);

    // 5: FF — conv1 via tf32 wmma tensor cores -> h1
    conv1_wmma_kernel<<<dim3(8, 65), 256>>>(p_mg, p_B1, p_c1bp, p_h1);
    //    conv2 + final residual + LN3 -> out
    gemm128t<2,4><<<dim3(1, 64), 256>>>(p_h1, p_B2, out, ROWS, 64, 1024,
                                        p_x1, p_mg, d1b, ln3w, ln3b, nullptr);

    (void)in_sizes; (void)n_in; (void)out_size;
}

// round 17
// speedup vs baseline: 1.2586x; 1.0131x over previous
#include <cuda_runtime.h>
#include <mma.h>
#include <cstdint>
#include <cstdio>

using namespace nvcuda;

// ---------------- problem dims ----------------
#define B8    8
#define N1    1024
#define DD    64
#define HH    4
#define DHH   16
#define DI    128
#define DS    64
#define ROWS  (B8*N1)          // 8192
#define BH    (B8*HH)          // 32
#define T1    1027             // conv1 output length
#define ROWS1 (B8*T1)          // 8216

// ---------------- scratch (static device globals; no allocation) ----------------
__device__ float g_xt   [ROWS*DD];
__device__ float g_wqkv [64*192];
__device__ float g_qkv  [ROWS*192];
__device__ float g_O    [ROWS*DD];
__device__ float g_x1   [ROWS*DD];
__device__ float g_xt2  [ROWS*DD];
__device__ float g_xz   [ROWS*256];
__device__ float g_u    [ROWS*DI];
__device__ float g_xdb  [ROWS*132];
__device__ float g_dt   [ROWS*DI];
__device__ float g_y    [ROWS*DI];
__device__ float g_mg   [ROWS*DD];
__device__ float g_B1   [256*512];      // interleaved (a,gate) columns
__device__ float g_c1bp [512];          // permuted conv1 bias
__device__ float g_h1   [ROWS1*256];
__device__ float g_B2   [1024*64];
__device__ unsigned g_maskbits[BH*N1*32];   // 1 bit per (bh,i,j); 32 words per row
__device__ int   g_mask_mode;

// ---------------- helpers ----------------
__device__ __forceinline__ float fast_exp(float x) {
    float t = x * 1.4426950408889634f;
    t = fminf(fmaxf(t, -126.0f), 126.0f);
    float fi = floorf(t);
    float f  = t - fi;
    float p = 0.0018775767f;
    p = fmaf(p, f, 0.0089893397f);
    p = fmaf(p, f, 0.055826318f);
    p = fmaf(p, f, 0.24015361f);
    p = fmaf(p, f, 0.69315308f);
    p = fmaf(p, f, 0.99999994f);
    return p * __int_as_float(((int)fi + 127) << 23);
}
__device__ __forceinline__ float sigmoid_f(float x) { return 1.0f / (1.0f + fast_exp(-x)); }
__device__ __forceinline__ float warp_sum(float v) {
    #pragma unroll
    for (int o = 16; o > 0; o >>= 1) v += __shfl_xor_sync(0xFFFFFFFFu, v, o);
    return v;
}
__device__ __forceinline__ float half_sum(float v) {   // reduce over 16-lane group
    v += __shfl_xor_sync(0xFFFFFFFFu, v, 1);
    v += __shfl_xor_sync(0xFFFFFFFFu, v, 2);
    v += __shfl_xor_sync(0xFFFFFFFFu, v, 4);
    v += __shfl_xor_sync(0xFFFFFFFFu, v, 8);
    return v;
}

// ---------------- init: mask sniff (block 0) + weight builders ----------------
__global__ void init_kernel(const unsigned int* __restrict__ m,
                            const float* __restrict__ Wq, const float* __restrict__ Wkv,
                            const float* __restrict__ c1w, const float* __restrict__ d1w,
                            const float* __restrict__ c1b) {
    if (blockIdx.x == 0) {
        __shared__ int cf, co;
        if (threadIdx.x == 0) { cf = 0; co = 0; }
        __syncthreads();
        int lf = 0, lo = 0;
        for (int k = 0; k < 16; k++) {
            unsigned w = m[threadIdx.x + k * 256];
            if (w == 0x3F800000u) lf++;
            else if (w != 0u && w != 1u) lo++;
        }
        atomicAdd(&cf, lf); atomicAdd(&co, lo);
        __syncthreads();
        if (threadIdx.x == 0)
            g_mask_mode = (cf > 32) ? 0 : ((co > 32) ? 2 : 1);
        return;
    }
    int idx = (blockIdx.x - 1) * 256 + threadIdx.x;
    if (idx < 64 * 192) {
        int k = idx / 192, c = idx % 192;
        g_wqkv[idx] = (c < 64) ? Wq[k * 64 + c] : Wkv[k * 128 + (c - 64)];
        return;
    }
    int i1 = idx - 64 * 192;
    if (i1 < 256 * 512) {
        int r = i1 >> 9, c = i1 & 511;
        int k = c >> 1, half = c & 1;
        int o = k + half * 256;
        int kt = r >> 6, ci = r & 63;
        g_B1[i1] = c1w[o * 256 + ci * 4 + kt];
        return;
    }
    int i2 = i1 - 256 * 512;
    if (i2 < 1024 * 64) {
        int r = i2 >> 6, co2 = i2 & 63;
        int ci = r >> 2, j = r & 3;
        g_B2[i2] = d1w[ci * 256 + co2 * 4 + j];
        return;
    }
    int i3 = i2 - 1024 * 64;
    if (i3 < 512) g_c1bp[i3] = c1b[(i3 >> 1) + (i3 & 1) * 256];
}

// ---------------- mask -> bitmask (perfectly coalesced ballot stream) ----------
__global__ void maskbits_kernel(const void* __restrict__ mask) {
    int warp = (blockIdx.x * blockDim.x + threadIdx.x) >> 5;
    int lane = threadIdx.x & 31;
    int mode = g_mask_mode;
    size_t ebase = (size_t)warp * 1024;
    #pragma unroll 4
    for (int k = 0; k < 32; k++) {
        size_t e = ebase + (size_t)k * 32 + lane;
        bool bit;
        if (mode == 0)      bit = ((const float*)mask)[e] != 0.0f;
        else if (mode == 1) bit = ((const int*)mask)[e] != 0;
        else                bit = ((const unsigned char*)mask)[e] != 0;
        unsigned w = __ballot_sync(0xFFFFFFFFu, bit);
        if (lane == 0) g_maskbits[warp * 32 + k] = w;
    }
}

// ---------------- layernorm (warp per row of 64) ----------------
__global__ void ln_kernel(const float* __restrict__ x, const float* __restrict__ w,
                          const float* __restrict__ b, float* __restrict__ out, int rows) {
    int warp = (blockIdx.x * blockDim.x + threadIdx.x) >> 5;
    int lane = threadIdx.x & 31;
    if (warp >= rows) return;
    const float* xr = x + (size_t)warp * 64;
    float v0 = xr[lane], v1 = xr[lane + 32];
    float mean = warp_sum(v0 + v1) * (1.0f / 64.0f);
    float d0 = v0 - mean, d1 = v1 - mean;
    float var = warp_sum(d0 * d0 + d1 * d1) * (1.0f / 64.0f);
    float inv = rsqrtf(var + 1e-5f);
    float* orow = out + (size_t)warp * 64;
    orow[lane]      = d0 * inv * w[lane]      + b[lane];
    orow[lane + 32] = d1 * inv * w[lane + 32] + b[lane + 32];
}

// ---------------- templated GEMM: 128x64 tile, 8x4 micro, double-buffered smem
// AMODE 0: A row-major [M,K]
// AMODE 3: A = (y + u*Dm)*silu(z) on-the-fly (A=g_y, p1=u, p2=xz, p3=Dm)
// EPI 0: C = acc (bounds-checked)
// EPI 1: x1 = 2*p0 + acc + p1[col]; C=x1; q0 = LN(x1; p2,p3)
// EPI 3: leaky + group-RMS(16): p0 = gamma
template<int AMODE, int EPI>
__global__ void __launch_bounds__(256, 2)
gemm128t(const float* __restrict__ A, const float* __restrict__ B,
         float* __restrict__ C, int M, int N, int K,
         const float* __restrict__ p0, const float* __restrict__ p1,
         const float* __restrict__ p2, const float* __restrict__ p3,
         const float* __restrict__ p4, float* __restrict__ q0) {
    __shared__ float As[2][16][132];
    __shared__ float Bs[2][16][68];
    int bm0 = blockIdx.y * 128, bn0 = blockIdx.x * 64;
    int tid = threadIdx.x;
    int tx = tid & 15, ty = tid >> 4;

    size_t abase[8];
    int    aaux[8];
    bool   avalid[8];
    #pragma unroll
    for (int i = 0; i < 8; i++) {
        int f = tid + i * 256;
        int gm = bm0 + (f >> 4);
        avalid[i] = (gm < M);
        int gmc = avalid[i] ? gm : 0;
        if (AMODE == 0) {
            abase[i] = (size_t)gmc * K; aaux[i] = 0;
        } else {
            abase[i] = (size_t)gmc * 128; aaux[i] = gmc * 256 + 128;
        }
    }

    float ra[8], rb[4];
    auto fetch = [&](int k0) {
        #pragma unroll
        for (int i = 0; i < 8; i++) {
            int f = tid + i * 256;
            int kk = f & 15;
            int k = k0 + kk;
            float v = 0.0f;
            if (AMODE == 0) {
                if (avalid[i]) v = A[abase[i] + k];
            } else {
                if (avalid[i]) {
                    float y  = A[abase[i] + k];
                    float uu = p1[abase[i] + k];
                    float z  = p2[aaux[i] + k];
                    v = (y + uu * p3[k]) * (z * sigmoid_f(z));
                }
            }
            ra[i] = v;
        }
        #pragma unroll
        for (int i = 0; i < 4; i++) {
            int f = tid + i * 256;
            int kk = f >> 6, n = f & 63;
            int gn = bn0 + n;
            rb[i] = (gn < N) ? B[(size_t)(k0 + kk) * N + gn] : 0.0f;
        }
    };
    auto stage = [&](int buf) {
        #pragma unroll
        for (int i = 0; i < 8; i++) {
            int f = tid + i * 256;
            As[buf][f & 15][f >> 4] = ra[i];
        }
        #pragma unroll
        for (int i = 0; i < 4; i++) {
            int f = tid + i * 256;
            Bs[buf][f >> 6][f & 63] = rb[i];
        }
    };

    fetch(0);
    stage(0);
    __syncthreads();

    float acc[8][4] = {};
    int T = K >> 4;
    for (int t = 0; t < T; t++) {
        int buf = t & 1;
        if (t + 1 < T) fetch((t + 1) << 4);
        #pragma unroll
        for (int kk = 0; kk < 16; kk++) {
            float4 a0 = *(const float4*)&As[buf][kk][ty * 8];
            float4 a1 = *(const float4*)&As[buf][kk][ty * 8 + 4];
            float4 b4 = *(const float4*)&Bs[buf][kk][tx * 4];
            float av[8] = {a0.x, a0.y, a0.z, a0.w, a1.x, a1.y, a1.z, a1.w};
            float bv[4] = {b4.x, b4.y, b4.z, b4.w};
            #pragma unroll
            for (int r = 0; r < 8; r++)
                #pragma unroll
                for (int c = 0; c < 4; c++)
                    acc[r][c] = fmaf(av[r], bv[c], acc[r][c]);
        }
        if (t + 1 < T) stage(buf ^ 1);
        __syncthreads();
    }

    if (EPI == 0) {
        #pragma unroll
        for (int r = 0; r < 8; r++) {
            int gm = bm0 + ty * 8 + r;
            if (gm < M) {
                #pragma unroll
                for (int c = 0; c < 4; c++) {
                    int gn = bn0 + tx * 4 + c;
                    if (gn < N) C[(size_t)gm * N + gn] = acc[r][c];
                }
            }
        }
    } else if (EPI == 1) {
        #pragma unroll
        for (int r = 0; r < 8; r++) {
            int gm = bm0 + ty * 8 + r;
            float v[4];
            #pragma unroll
            for (int c = 0; c < 4; c++) {
                int gn = tx * 4 + c;
                v[c] = 2.0f * p0[(size_t)gm * 64 + gn] + acc[r][c] + p1[gn];
                C[(size_t)gm * 64 + gn] = v[c];
            }
            float s = half_sum(v[0] + v[1] + v[2] + v[3]);
            float mean = s * (1.0f / 64.0f);
            float d[4], ss = 0.0f;
            #pragma unroll
            for (int c = 0; c < 4; c++) { d[c] = v[c] - mean; ss = fmaf(d[c], d[c], ss); }
            ss = half_sum(ss);
            float inv = rsqrtf(ss * (1.0f / 64.0f) + 1e-5f);
            #pragma unroll
            for (int c = 0; c < 4; c++) {
                int gn = tx * 4 + c;
                q0[(size_t)gm * 64 + gn] = d[c] * inv * p2[gn] + p3[gn];
            }
        }
    } else {
        // EPI 3: leaky relu + group-RMS(16)
        #pragma unroll
        for (int r = 0; r < 8; r++) {
            int gm = bm0 + ty * 8 + r;
            float v[4], ss = 0.0f;
            #pragma unroll
            for (int c = 0; c < 4; c++) {
                float xv = acc[r][c];
                xv = (xv >= 0.0f) ? xv : 0.01f * xv;
                v[c] = xv; ss = fmaf(xv, xv, ss);
            }
            ss += __shfl_xor_sync(0xFFFFFFFFu, ss, 1);
            ss += __shfl_xor_sync(0xFFFFFFFFu, ss, 2);
            float sc = 1.0f / (sqrtf(ss) * 0.25f + 1e-5f);
            #pragma unroll
            for (int c = 0; c < 4; c++) {
                int gn = tx * 4 + c;
                C[(size_t)gm * 64 + gn] = v[c] * sc * p0[gn];
            }
        }
    }
}

// ---------------- conv1 via tf32 wmma tensor cores ---------------------------
// C[ROWS1, 512] = im2col(g_mg) @ g_B1, gated epilogue -> g_h1[ROWS1, 256]
__global__ void __launch_bounds__(256)
conv1_wmma_kernel(const float* __restrict__ mg, const float* __restrict__ B1,
                  const float* __restrict__ c1bp, float* __restrict__ h1) {
    __shared__ float sm[128 * 68];
    float* As = sm;                          // [128][20]
    float* Bs = sm + 128 * 20;               // [16][68]
    float* Co = sm;                          // [128][68] epilogue reuse

    int bn0 = blockIdx.x * 64;
    int bm0 = blockIdx.y * 128;
    int tid = threadIdx.x;
    int wid = tid >> 5;
    int warp_m = wid & 3, warp_n = wid >> 2;

    int arow_t[8]; int abase[8]; bool avalid[8];
    #pragma unroll
    for (int i = 0; i < 8; i++) {
        int f = tid + i * 256;
        int gm = bm0 + (f >> 4);
        avalid[i] = (gm < ROWS1);
        int gmc = avalid[i] ? gm : 0;
        int b = gmc / 1027;
        arow_t[i] = gmc - b * 1027;
        abase[i] = (b << 10) * 64;
    }

    wmma::fragment<wmma::accumulator, 16, 16, 8, float> c[2][2];
    #pragma unroll
    for (int mi = 0; mi < 2; mi++)
        #pragma unroll
        for (int ni = 0; ni < 2; ni++)
            wmma::fill_fragment(c[mi][ni], 0.0f);

    for (int k0 = 0; k0 < 256; k0 += 16) {
        #pragma unroll
        for (int i = 0; i < 8; i++) {
            int f = tid + i * 256;
            int m = f >> 4, kk = f & 15;
            int k = k0 + kk;
            int kt = k >> 6, ci = k & 63;
            int s = arow_t[i] + kt - 3;
            float v = 0.0f;
            if (avalid[i] && s >= 0 && s < 1024) v = mg[abase[i] + s * 64 + ci];
            As[m * 20 + kk] = v;
        }
        #pragma unroll
        for (int i = 0; i < 4; i++) {
            int f = tid + i * 256;
            int kk = f >> 6, n = f & 63;
            Bs[kk * 68 + n] = B1[(k0 + kk) * 512 + bn0 + n];
        }
        __syncthreads();
        #pragma unroll
        for (int ks = 0; ks < 16; ks += 8) {
            wmma::fragment<wmma::matrix_a, 16, 16, 8, wmma::precision::tf32, wmma::row_major> a[2];
            wmma::fragment<wmma::matrix_b, 16, 16, 8, wmma::precision::tf32, wmma::row_major> bf[2];
            #pragma unroll
            for (int mi = 0; mi < 2; mi++) {
                wmma::load_matrix_sync(a[mi], &As[(warp_m * 32 + mi * 16) * 20 + ks], 20);
                #pragma unroll
                for (int t = 0; t < a[mi].num_elements; t++)
                    a[mi].x[t] = wmma::__float_to_tf32(a[mi].x[t]);
            }
            #pragma unroll
            for (int ni = 0; ni < 2; ni++) {
                wmma::load_matrix_sync(bf[ni], &Bs[ks * 68 + warp_n * 32 + ni * 16], 68);
                #pragma unroll
                for (int t = 0; t < bf[ni].num_elements; t++)
                    bf[ni].x[t] = wmma::__float_to_tf32(bf[ni].x[t]);
            }
            #pragma unroll
            for (int mi = 0; mi < 2; mi++)
                #pragma unroll
                for (int ni = 0; ni < 2; ni++)
                    wmma::mma_sync(c[mi][ni], a[mi], bf[ni], c[mi][ni]);
        }
        __syncthreads();
    }

    #pragma unroll
    for (int mi = 0; mi < 2; mi++)
        #pragma unroll
        for (int ni = 0; ni < 2; ni++)
            wmma::store_matrix_sync(&Co[(warp_m * 32 + mi * 16) * 68 + warp_n * 32 + ni * 16],
                                    c[mi][ni], 68, wmma::mem_row_major);
    __syncthreads();
    int hbase = bn0 >> 1;
    for (int f = tid; f < 128 * 32; f += 256) {
        int m = f >> 5, hc = f & 31;
        int gm = bm0 + m;
        if (gm < ROWS1) {
            float a = Co[m * 68 + hc * 2]     + c1bp[bn0 + hc * 2];
            float g = Co[m * 68 + hc * 2 + 1] + c1bp[bn0 + hc * 2 + 1];
            h1[(size_t)gm * 256 + hbase + hc] = a * (g * sigmoid_f(g));
        }
    }
}

// ---------------- conv2 via tf32 wmma + final residual + LN3 -----------------
// out[8192,64] = LN3( x1 + mg + 0.5*(im2col(h1) @ B2 + d1b) )
// grid (1, 64); block owns rows [bm0, bm0+128) completely (N=64).
__global__ void __launch_bounds__(256)
conv2_wmma_kernel(const float* __restrict__ h1, const float* __restrict__ B2,
                  const float* __restrict__ x1, const float* __restrict__ mg,
                  const float* __restrict__ d1b, const float* __restrict__ w3,
                  const float* __restrict__ b3, float* __restrict__ out) {
    __shared__ float sm[128 * 68];
    float* As = sm;                          // [128][20]
    float* Bs = sm + 128 * 20;               // [16][68]
    float* Co = sm;                          // [128][68] epilogue reuse

    int bm0 = blockIdx.y * 128;
    int tid = threadIdx.x;
    int wid = tid >> 5;
    int warp_m = wid & 3, warp_n = wid >> 2;

    // per-slot A row bases (rows always valid: 64*128 = 8192 = ROWS)
    size_t abase[8];
    #pragma unroll
    for (int i = 0; i < 8; i++) {
        int f = tid + i * 256;
        int gm = bm0 + (f >> 4);
        int b = gm >> 10, s = gm & 1023;
        abase[i] = ((size_t)b * 1027 + s) * 256;
    }

    wmma::fragment<wmma::accumulator, 16, 16, 8, float> c[2][2];
    #pragma unroll
    for (int mi = 0; mi < 2; mi++)
        #pragma unroll
        for (int ni = 0; ni < 2; ni++)
            wmma::fill_fragment(c[mi][ni], 0.0f);

    float ra[8], rb[4];
    auto fetch = [&](int k0) {
        #pragma unroll
        for (int i = 0; i < 8; i++) {
            int f = tid + i * 256;
            int kk = f & 15;
            int k = k0 + kk;
            int ci = k >> 2, j = k & 3;
            ra[i] = h1[abase[i] + (size_t)(3 - j) * 256 + ci];
        }
        #pragma unroll
        for (int i = 0; i < 4; i++) {
            int f = tid + i * 256;
            int kk = f >> 6, n = f & 63;
            rb[i] = B2[(size_t)(k0 + kk) * 64 + n];
        }
    };
    auto stage = [&]() {
        #pragma unroll
        for (int i = 0; i < 8; i++) {
            int f = tid + i * 256;
            As[(f >> 4) * 20 + (f & 15)] = ra[i];
        }
        #pragma unroll
        for (int i = 0; i < 4; i++) {
            int f = tid + i * 256;
            Bs[(f >> 6) * 68 + (f & 63)] = rb[i];
        }
    };

    fetch(0);
    for (int t = 0; t < 64; t++) {
        stage();
        __syncthreads();
        if (t + 1 < 64) fetch((t + 1) << 4);     // global loads overlap mma
        #pragma unroll
        for (int ks = 0; ks < 16; ks += 8) {
            wmma::fragment<wmma::matrix_a, 16, 16, 8, wmma::precision::tf32, wmma::row_major> a[2];
            wmma::fragment<wmma::matrix_b, 16, 16, 8, wmma::precision::tf32, wmma::row_major> bf[2];
            #pragma unroll
            for (int mi = 0; mi < 2; mi++) {
                wmma::load_matrix_sync(a[mi], &As[(warp_m * 32 + mi * 16) * 20 + ks], 20);
                #pragma unroll
                for (int tt = 0; tt < a[mi].num_elements; tt++)
                    a[mi].x[tt] = wmma::__float_to_tf32(a[mi].x[tt]);
            }
            #pragma unroll
            for (int ni = 0; ni < 2; ni++) {
                wmma::load_matrix_sync(bf[ni], &Bs[ks * 68 + warp_n * 32 + ni * 16], 68);
                #pragma unroll
                for (int tt = 0; tt < bf[ni].num_elements; tt++)
                    bf[ni].x[tt] = wmma::__float_to_tf32(bf[ni].x[tt]);
            }
            #pragma unroll
            for (int mi = 0; mi < 2; mi++)
                #pragma unroll
                for (int ni = 0; ni < 2; ni++)
                    wmma::mma_sync(c[mi][ni], a[mi], bf[ni], c[mi][ni]);
        }
        __syncthreads();
    }

    #pragma unroll
    for (int mi = 0; mi < 2; mi++)
        #pragma unroll
        for (int ni = 0; ni < 2; ni++)
            wmma::store_matrix_sync(&Co[(warp_m * 32 + mi * 16) * 68 + warp_n * 32 + ni * 16],
                                    c[mi][ni], 68, wmma::mem_row_major);
    __syncthreads();

    // epilogue: v = x1 + mg + 0.5*(acc + d1b); out = LN3(v)
    int tx = tid & 15, ty = tid >> 4;
    #pragma unroll
    for (int r = 0; r < 8; r++) {
        int gm = bm0 + ty * 8 + r;
        float v[4];
        #pragma unroll
        for (int cc = 0; cc < 4; cc++) {
            int gn = tx * 4 + cc;
            size_t ix = (size_t)gm * 64 + gn;
            v[cc] = x1[ix] + mg[ix] + 0.5f * (Co[(ty * 8 + r) * 68 + gn] + d1b[gn]);
        }
        float s = half_sum(v[0] + v[1] + v[2] + v[3]);
        float mean = s * (1.0f / 64.0f);
        float d[4], ss = 0.0f;
        #pragma unroll
        for (int cc = 0; cc < 4; cc++) { d[cc] = v[cc] - mean; ss = fmaf(d[cc], d[cc], ss); }
        ss = half_sum(ss);
        float inv = rsqrtf(ss * (1.0f / 64.0f) + 1e-5f);
        #pragma unroll
        for (int cc = 0; cc < 4; cc++) {
            int gn = tx * 4 + cc;
            out[(size_t)gm * 64 + gn] = d[cc] * inv * w3[gn] + b3[gn];
        }
    }
}

// ---------------- fused flash attention (R9 structure + smem bitmask) ----------
__global__ void __launch_bounds__(256)
flash_kernel(const float* __restrict__ qkv, const float* __restrict__ relemb,
             float* __restrict__ O) {
    int it = blockIdx.x, bh = blockIdx.y;
    int b = bh >> 2, h = bh & 3;
    int i0 = it * 64;
    __shared__ float qT[16][68];
    __shared__ float kT[16][68];
    __shared__ float vT[16][68];
    __shared__ float relT[16][132];
    __shared__ float osm[64][17];
    __shared__ float rsm[64];
    __shared__ unsigned msk_sh[64 * 32];
    int tid = threadIdx.x, tx = tid & 15, ty = tid >> 4;

    const float* qb = qkv + (size_t)(b * 1024 + i0) * 192 + h * 16;
    for (int f = tid; f < 1024; f += 256) { int r = f >> 4, d = f & 15; qT[d][r] = qb[r * 192 + d]; }
    {
        const unsigned* mb = g_maskbits + ((size_t)bh * 1024 + i0) * 32;
        for (int f = tid; f < 2048; f += 256) msk_sh[f] = mb[f];
    }

    float acc[4][16] = {};
    float rsum[4] = {};
    int lbase = (ty - tx) * 4 + 60;
    int bitb = (tx * 4) & 31;
    int wofs = tx >> 3;

    for (int jt = 0; jt < 16; jt++) {
        int j0 = jt * 64;
        __syncthreads();
        const float* kb = qkv + (size_t)(b * 1024 + j0) * 192 + 64 + h * 16;
        for (int f = tid; f < 1024; f += 256) {
            int r = f >> 4, d = f & 15;
            kT[d][r] = kb[r * 192 + d];
            vT[d][r] = kb[r * 192 + 64 + d];
        }
        int pbase = i0 - j0 + 449;
        for (int f = tid; f < 127 * 16; f += 256) {
            int m = f >> 4, d = f & 15;
            int p = min(max(pbase + m, 0), 1024);
            relT[d][m] = relemb[p * 16 + d];
        }
        __syncthreads();

        float s[4][4] = {};
        #pragma unroll
        for (int d = 0; d < 16; d++) {
            float4 aq4 = *(const float4*)&qT[d][ty * 4];
            float4 bk4 = *(const float4*)&kT[d][tx * 4];
            float aq[4] = {aq4.x, aq4.y, aq4.z, aq4.w};
            float bk[4] = {bk4.x, bk4.y, bk4.z, bk4.w};
            float rl[7];
            #pragma unroll
            for (int m = 0; m < 7; m++) rl[m] = relT[d][lbase + m];
            #pragma unroll
            for (int r = 0; r < 4; r++)
                #pragma unroll
                for (int c = 0; c < 4; c++)
                    s[r][c] = fmaf(aq[r], bk[c] + rl[r - c + 3], s[r][c]);
        }

        float e[4][4];
        int wbase = (j0 >> 5) + wofs;
        #pragma unroll
        for (int r = 0; r < 4; r++) {
            unsigned w = msk_sh[(ty * 4 + r) * 32 + wbase];
            e[r][0] = ((w >> (bitb    )) & 1u) ? 0.0f : fast_exp(s[r][0] * 0.25f);
            e[r][1] = ((w >> (bitb + 1)) & 1u) ? 0.0f : fast_exp(s[r][1] * 0.25f);
            e[r][2] = ((w >> (bitb + 2)) & 1u) ? 0.0f : fast_exp(s[r][2] * 0.25f);
            e[r][3] = ((w >> (bitb + 3)) & 1u) ? 0.0f : fast_exp(s[r][3] * 0.25f);
            rsum[r] += e[r][0] + e[r][1] + e[r][2] + e[r][3];
        }

        #pragma unroll
        for (int d = 0; d < 16; d++) {
            float4 v4 = *(const float4*)&vT[d][tx * 4];
            #pragma unroll
            for (int r = 0; r < 4; r++)
                acc[r][d] = fmaf(e[r][0], v4.x,
                            fmaf(e[r][1], v4.y,
                            fmaf(e[r][2], v4.z,
                            fmaf(e[r][3], v4.w, acc[r][d]))));
        }
    }

    #pragma unroll
    for (int r = 0; r < 4; r++) {
        #pragma unroll
        for (int d = 0; d < 16; d++) acc[r][d] = half_sum(acc[r][d]);
        rsum[r] = half_sum(rsum[r]);
    }
    __syncthreads();
    if (tx == 0) {
        #pragma unroll
        for (int r = 0; r < 4; r++) {
            #pragma unroll
            for (int d = 0; d < 16; d++) osm[ty * 4 + r][d] = acc[r][d];
            rsm[ty * 4 + r] = rsum[r];
        }
    }
    __syncthreads();
    for (int f = tid; f < 1024; f += 256) {
        int r = f >> 4, d = f & 15;
        O[(size_t)(b * 1024 + i0 + r) * 64 + h * 16 + d] = osm[r][d] / rsm[r];
    }
}

// ---------------- remaining elementwise stages ----------------
__global__ void convsilu_kernel(const float* __restrict__ convw, const float* __restrict__ convb) {
    int idx = blockIdx.x * blockDim.x + threadIdx.x;
    if (idx >= ROWS * DI) return;
    int d = idx & 127, t = (idx >> 7) & 1023, b = idx >> 17;
    float acc = convb[d];
    #pragma unroll
    for (int k = 0; k < 4; k++) {
        int s = t + k - 3;
        if (s >= 0) acc = fmaf(g_xz[(size_t)((b << 10) + s) * 256 + d], convw[d * 4 + k], acc);
    }
    g_u[idx] = acc * sigmoid_f(acc);
}
__global__ void dtprep_kernel(const float* __restrict__ Wdt, const float* __restrict__ bdt) {
    int idx = blockIdx.x * blockDim.x + threadIdx.x;
    if (idx >= ROWS * DI) return;
    int d = idx & 127, bt = idx >> 7;
    float x = bdt[d];
    #pragma unroll
    for (int r = 0; r < 4; r++) x = fmaf(g_xdb[(size_t)bt * 132 + r], Wdt[r * 128 + d], x);
    g_dt[idx] = (x > 20.0f) ? x : log1pf(fast_exp(x));
}
__global__ void scan_kernel(const float* __restrict__ Alog) {
    int w = (blockIdx.x * blockDim.x + threadIdx.x) >> 5;
    int lane = threadIdx.x & 31;
    int b = w >> 7, d = w & 127;
    float A0 = -__expf(Alog[d * 64 + lane]);
    float A1 = -__expf(Alog[d * 64 + lane + 32]);
    float h0 = 0.0f, h1 = 0.0f;
    const float* dtp = g_dt + (size_t)b * 1024 * 128 + d;
    const float* up  = g_u  + (size_t)b * 1024 * 128 + d;
    const float* xp  = g_xdb + (size_t)b * 1024 * 132;
    float* yp = g_y + (size_t)b * 1024 * 128 + d;
    #pragma unroll 4
    for (int t = 0; t < 1024; t++) {
        float dtv = dtp[t << 7];
        float uv  = up[t << 7];
        float B0 = xp[t * 132 + 4 + lane],  B1 = xp[t * 132 + 36 + lane];
        float C0 = xp[t * 132 + 68 + lane], C1 = xp[t * 132 + 100 + lane];
        float du = dtv * uv;
        h0 = fmaf(h0, __expf(dtv * A0), du * B0);
        h1 = fmaf(h1, __expf(dtv * A1), du * B1);
        float p = fmaf(h0, C0, h1 * C1);
        p = warp_sum(p);
        if (lane == 0) yp[t << 7] = p;
    }
}

// ---------------- launch ----------------
static void* dev_ptr(const void* sym) { void* p = nullptr; cudaGetSymbolAddress(&p, sym); return p; }

extern "C" void kernel_launch(void* const* d_in, const int* in_sizes, int n_in,
                              void* d_out, int out_size) {
    const float* x      = (const float*)d_in[0];
    const void*  dmask  = d_in[1];
    const float* ln1w   = (const float*)d_in[2];
    const float* ln1b   = (const float*)d_in[3];
    const float* Wq     = (const float*)d_in[4];
    const float* Wkv    = (const float*)d_in[5];
    const float* Wo     = (const float*)d_in[6];
    const float* bo     = (const float*)d_in[7];
    const float* relemb = (const float*)d_in[8];
    const float* ln2w   = (const float*)d_in[9];
    const float* ln2b   = (const float*)d_in[10];
    const float* Win    = (const float*)d_in[11];
    const float* convw  = (const float*)d_in[12];
    const float* convb  = (const float*)d_in[13];
    const float* Wxproj = (const float*)d_in[14];
    const float* Wdt    = (const float*)d_in[15];
    const float* bdt    = (const float*)d_in[16];
    const float* Alog   = (const float*)d_in[17];
    const float* Dm     = (const float*)d_in[18];
    const float* Wout   = (const float*)d_in[19];
    const float* gamma  = (const float*)d_in[20];
    const float* c1w    = (const float*)d_in[21];
    const float* c1b    = (const float*)d_in[22];
    const float* d1w    = (const float*)d_in[23];
    const float* d1b    = (const float*)d_in[24];
    const float* ln3w   = (const float*)d_in[25];
    const float* ln3b   = (const float*)d_in[26];
    float* out = (float*)d_out;

    float* p_xt    = (float*)dev_ptr(g_xt);
    float* p_wqkv  = (float*)dev_ptr(g_wqkv);
    float* p_qkv   = (float*)dev_ptr(g_qkv);
    float* p_O     = (float*)dev_ptr(g_O);
    float* p_x1    = (float*)dev_ptr(g_x1);
    float* p_xt2   = (float*)dev_ptr(g_xt2);
    float* p_xz    = (float*)dev_ptr(g_xz);
    float* p_u     = (float*)dev_ptr(g_u);
    float* p_xdb   = (float*)dev_ptr(g_xdb);
    float* p_y     = (float*)dev_ptr(g_y);
    float* p_mg    = (float*)dev_ptr(g_mg);
    float* p_B1    = (float*)dev_ptr(g_B1);
    float* p_c1bp  = (float*)dev_ptr(g_c1bp);
    float* p_h1    = (float*)dev_ptr(g_h1);
    float* p_B2    = (float*)dev_ptr(g_B2);

    // 0: mask sniff + weight rearrangement, then bit-compress mask
    int build_elems = 64*192 + 256*512 + 1024*64 + 512;
    init_kernel<<<1 + (build_elems + 255) / 256, 256>>>(
        (const unsigned int*)dmask, Wq, Wkv, c1w, d1w, c1b);
    maskbits_kernel<<<4096, 256>>>(dmask);

    // 1: LN1 + QKV projection
    ln_kernel<<<1024, 256>>>(x, ln1w, ln1b, p_xt, ROWS);
    gemm128t<0,0><<<dim3(3, 64), 256>>>(p_xt, p_wqkv, p_qkv, ROWS, 192, 64,
                                        nullptr, nullptr, nullptr, nullptr, nullptr, nullptr);

    // 2: fused flash attention (bitmask from smem)
    flash_kernel<<<dim3(16, BH), 256>>>(p_qkv, relemb, p_O);

    // 3: Wo proj + bias + double residual + LN2 -> g_x1, g_xt2
    gemm128t<0,1><<<dim3(1, 64), 256>>>(p_O, Wo, p_x1, ROWS, 64, 64,
                                        x, bo, ln2w, ln2b, nullptr, p_xt2);

    // 4: Mamba
    gemm128t<0,0><<<dim3(4, 64), 256>>>(p_xt2, Win, p_xz, ROWS, 256, 64,
                                        nullptr, nullptr, nullptr, nullptr, nullptr, nullptr);
    convsilu_kernel<<<(ROWS * DI + 255) / 256, 256>>>(convw, convb);
    gemm128t<0,0><<<dim3(3, 64), 256>>>(p_u, Wxproj, p_xdb, ROWS, 132, DI,
                                        nullptr, nullptr, nullptr, nullptr, nullptr, nullptr);
    dtprep_kernel<<<(ROWS * DI + 255) / 256, 256>>>(Wdt, bdt);
    scan_kernel<<<128, 256>>>(Alog);
    // Wout: on-the-fly ym (amode3) + leaky+groupRMS (epi3) -> g_mg
    gemm128t<3,3><<<dim3(1, 64), 256>>>(p_y, Wout, p_mg, ROWS, 64, DI,
                                        gamma, p_u, p_xz, Dm, nullptr, nullptr);

    // 5: FF — conv1 via tf32 wmma tensor cores -> h1
    conv1_wmma_kernel<<<dim3(8, 65), 256>>>(p_mg, p_B1, p_c1bp, p_h1);
    //    conv2 via tf32 wmma + final residual + LN3 -> out
    conv2_wmma_kernel<<<dim3(1, 64), 256>>>(p_h1, p_B2, p_x1, p_mg, d1b, ln3w, ln3b, out);

    (void)in_sizes; (void)n_in; (void)out_size;
}